// round 14
// baseline (speedup 1.0000x reference)
#include <cuda_runtime.h>
#include <math.h>
#include <stdint.h>

#define NPTS 524288
#define TSZ  524288
#define NTHREADS 256
#define NWARPS_BLK 8
#define NBLOCKS 296
#define FULL 0xffffffffu
#define NPAIR 5   // 10 points per warp iteration

typedef unsigned long long u64;

// ---- shared memory layout (float offsets) ----
#define OFF_WS0PK4  0       // [16][32] float4
#define OFF_WS0TPK4 2048    // [16][32] float4
#define OFF_WS1PK4  4096    // [16][16] float4
#define OFF_WC1PK   5120    // [32][32] float4
#define OFF_WC0SH4  9216    // [8][32] float4
#define OFF_WC0GE4  10240   // [8][32] float4
#define OFF_WN0PK4  11264   // [8][32] float4
#define OFF_WM0PK2  12288   // [8][32] float2
#define OFF_WC2     12800   // [64][3]
#define OFF_WN1     12992   // [64][3]
#define OFF_WM1     13184   // [32]
#define OFF_BM0     13216   // [32]
#define OFF_BM1     13248   // [1]
#define OFF_WS10    13250   // [64] ws1 column 0
#define OFF_DF      13316   // 8 warps * 480 u64 = 7680 floats
#define OFF_ABUF    20996   // 8 warps * 320 u64 = 5120 floats (16B aligned)
#define OFF_XBUF    26116   // 8 warps * 128 floats (2 buffers x 64)
#define SMEM_FLOATS 27140

struct HGParams { int res[16]; int dense[16]; };

__device__ __forceinline__ u64 pk(float lo, float hi) {
    u64 r; asm("mov.b64 %0,{%1,%2};" : "=l"(r) : "f"(lo), "f"(hi)); return r;
}
__device__ __forceinline__ void upk(u64 v, float& lo, float& hi) {
    asm("mov.b64 {%0,%1},%2;" : "=f"(lo), "=f"(hi) : "l"(v));
}
__device__ __forceinline__ u64 bc2(float w) { return pk(w, w); }
__device__ __forceinline__ u64 fma2(u64 a, u64 b, u64 c) {
    u64 d; asm("fma.rn.f32x2 %0,%1,%2,%3;" : "=l"(d) : "l"(a), "l"(b), "l"(c)); return d;
}
__device__ __forceinline__ u64 mul2(u64 a, u64 b) {
    u64 d; asm("mul.rn.f32x2 %0,%1,%2;" : "=l"(d) : "l"(a), "l"(b)); return d;
}
__device__ __forceinline__ u64 add2(u64 a, u64 b) {
    u64 d; asm("add.rn.f32x2 %0,%1,%2;" : "=l"(d) : "l"(a), "l"(b)); return d;
}
__device__ __forceinline__ u64 relu2(u64 v) {
    float a, b; upk(v, a, b); return pk(fmaxf(a, 0.f), fmaxf(b, 0.f));
}
__device__ __forceinline__ u64 allsum2(u64 v) {
    #pragma unroll
    for (int o = 16; o > 0; o >>= 1) v = add2(v, __shfl_xor_sync(FULL, v, o));
    return v;
}
__device__ __forceinline__ float sigm(float v) { return 1.0f / (1.0f + expf(-v)); }
__device__ __forceinline__ float sel3(int lane, float a, float b, float c) {
    return lane == 0 ? a : (lane == 1 ? b : c);
}

extern __shared__ float smem[];

__global__ __launch_bounds__(NTHREADS, 2) void nerf_kernel(
    const float* __restrict__ x,
    const float* __restrict__ tables,
    const float* __restrict__ ws0, const float* __restrict__ ws1,
    const float* __restrict__ wc0, const float* __restrict__ wc1, const float* __restrict__ wc2,
    const float* __restrict__ wn0, const float* __restrict__ wn1,
    const float* __restrict__ wm0, const float* __restrict__ bm0,
    const float* __restrict__ wm1, const float* __restrict__ bm1,
    float* __restrict__ out, HGParams prm)
{
    const int tid = threadIdx.x;
    {
        float4* p0 = (float4*)(smem + OFF_WS0PK4);
        for (int i = tid; i < 512; i += NTHREADS) { int r = i >> 5, c = i & 31;
            p0[i] = make_float4(ws0[(2*r)*64+c], ws0[(2*r)*64+c+32], ws0[(2*r+1)*64+c], ws0[(2*r+1)*64+c+32]); }
        float4* pt4 = (float4*)(smem + OFF_WS0TPK4);
        for (int i = tid; i < 512; i += NTHREADS) { int r = i >> 5, c = i & 31;
            pt4[i] = make_float4(ws0[c*64+2*r], ws0[c*64+2*r+32], ws0[c*64+2*r+1], ws0[c*64+2*r+1+32]); }
        float4* p14 = (float4*)(smem + OFF_WS1PK4);
        for (int i = tid; i < 256; i += NTHREADS) { int r = i >> 4, j = i & 15;
            p14[i] = make_float4(ws1[(2*r)*16+j], ws1[(2*r+32)*16+j], ws1[(2*r+1)*16+j], ws1[(2*r+1+32)*16+j]); }
        float4* pc1 = (float4*)(smem + OFF_WC1PK);
        for (int i = tid; i < 1024; i += NTHREADS) { int kk = i >> 5, c = i & 31;
            pc1[i] = make_float4(wc1[kk*64+c], wc1[kk*64+c+32], wc1[(kk+32)*64+c], wc1[(kk+32)*64+c+32]); }
        float4* psh = (float4*)(smem + OFF_WC0SH4);
        for (int i = tid; i < 256; i += NTHREADS) { int r = i >> 5, c = i & 31;
            psh[i] = make_float4(wc0[(2*r)*64+c], wc0[(2*r)*64+c+32], wc0[(2*r+1)*64+c], wc0[(2*r+1)*64+c+32]); }
        float4* pge = (float4*)(smem + OFF_WC0GE4);
        for (int i = tid; i < 256; i += NTHREADS) { int r = i >> 5, c = i & 31;
            int r0 = 16 + 2*r, r1 = 17 + 2*r;
            float w2 = (r1 <= 30) ? wc0[r1*64+c] : 0.f;
            float w3 = (r1 <= 30) ? wc0[r1*64+c+32] : 0.f;
            pge[i] = make_float4(wc0[r0*64+c], wc0[r0*64+c+32], w2, w3); }
        float4* pn4 = (float4*)(smem + OFF_WN0PK4);
        for (int i = tid; i < 256; i += NTHREADS) { int r = i >> 5, c = i & 31;
            int r1 = 2*r+1;
            float w2 = (r1 <= 14) ? wn0[r1*64+c] : 0.f;
            float w3 = (r1 <= 14) ? wn0[r1*64+c+32] : 0.f;
            pn4[i] = make_float4(wn0[(2*r)*64+c], wn0[(2*r)*64+c+32], w2, w3); }
        float2* pm2 = (float2*)(smem + OFF_WM0PK2);
        for (int i = tid; i < 256; i += NTHREADS) { int r = i >> 5, c = i & 31;
            int r1 = 2*r+1;
            float w1 = (r1 <= 14) ? wm0[r1*32+c] : 0.f;
            pm2[i] = make_float2(wm0[(2*r)*32+c], w1); }
        for (int i = tid; i < 192; i += NTHREADS) smem[OFF_WC2 + i] = wc2[i];
        for (int i = tid; i < 192; i += NTHREADS) smem[OFF_WN1 + i] = wn1[i];
        for (int i = tid; i < 32;  i += NTHREADS) smem[OFF_WM1 + i] = wm1[i];
        for (int i = tid; i < 32;  i += NTHREADS) smem[OFF_BM0 + i] = bm0[i];
        for (int i = tid; i < 64;  i += NTHREADS) smem[OFF_WS10 + i] = ws1[i * 16];
        if (tid == 0) smem[OFF_BM1] = bm1[0];
    }
    __syncthreads();

    const int lane = tid & 31;
    const int warpInBlk = tid >> 5;
    const int gwarp = blockIdx.x * NWARPS_BLK + warpInBlk;
    const int nwarp = gridDim.x * NWARPS_BLK;
    const int j16 = lane & 15;

    const int lvl = lane >> 1;
    const int half = lane & 1;
    const float sxsign = half ? 1.f : -1.f;
    const int res = prm.res[lvl];
    const int dense = prm.dense[lvl];
    const int resm1 = res - 1;
    const float rm1 = (float)resm1;
    const float gscale = rm1 * 0.5f;
    const unsigned my = dense ? (unsigned)res : 2654435761u;
    const unsigned mz = dense ? (unsigned)(res * res) : 805459861u;
    const float2* __restrict__ tabl = ((const float2*)tables) + (size_t)lvl * TSZ;

    const float4* ws0pk4  = (const float4*)(smem + OFF_WS0PK4);
    const float4* ws0tpk4 = (const float4*)(smem + OFF_WS0TPK4);
    const float4* ws1pk4  = (const float4*)(smem + OFF_WS1PK4);
    const float4* wc1pk   = (const float4*)(smem + OFF_WC1PK);
    const float4* wc0sh4  = (const float4*)(smem + OFF_WC0SH4);
    const float4* wc0ge4  = (const float4*)(smem + OFF_WC0GE4);
    const float4* wn0pk4  = (const float4*)(smem + OFF_WN0PK4);
    const float2* wm0pk2  = (const float2*)(smem + OFF_WM0PK2);
    const float* swc2 = smem + OFF_WC2;
    const float* swn1 = smem + OFF_WN1;
    const float* swm1 = smem + OFF_WM1;
    const float* sbm0 = smem + OFF_BM0;
    const float* sws10 = smem + OFF_WS10;
    u64* dfw  = ((u64*)(smem + OFF_DF))  + warpInBlk * (NPAIR * 3 * 32);
    u64* abw  = ((u64*)(smem + OFF_ABUF)) + warpInBlk * (NPAIR * 64);
    float* xbw = smem + OFF_XBUF + warpInBlk * 128;            // 2 buffers x 64 floats

    // ---- prologue: prefetch x for first iteration into buffer 0 ----
    {
        long long base = (long long)(gwarp * (2 * NPAIR)) * 6;
        long long lim = (long long)NPTS * 6;
        if (base + lane < lim) xbw[lane] = __ldg(x + base + lane);
        if (lane < 28 && base + 32 + lane < lim) xbw[32 + lane] = __ldg(x + base + 32 + lane);
    }
    __syncwarp();

    int it = 0;
    for (int pbase = gwarp * (2 * NPAIR); pbase < NPTS; pbase += nwarp * (2 * NPAIR), ++it) {
        const float* xc = xbw + ((it & 1) * 64);

        // ================= hashgrid gather (x from smem buffer) =================
        u64 encP[NPAIR];
        #pragma unroll
        for (int P = 0; P < NPAIR; ++P) {
            float e2[2], gx2[2], gy2[2], gz2[2];
            #pragma unroll
            for (int q = 0; q < 2; ++q) {
                const float* xp = xc + (2 * P + q) * 6;
                float X = fminf(fmaxf((xp[0] + 1.0f) * 0.5f, 0.0f), 1.0f);
                float Y = fminf(fmaxf((xp[1] + 1.0f) * 0.5f, 0.0f), 1.0f);
                float Z = fminf(fmaxf((xp[2] + 1.0f) * 0.5f, 0.0f), 1.0f);
                float px = X * rm1, py = Y * rm1, pz = Z * rm1;
                float fpx = floorf(px), fpy = floorf(py), fpz = floorf(pz);
                float fx = px - fpx, fy = py - fpy, fz = pz - fpz;
                int ix = (int)fpx, iy = (int)fpy, iz = (int)fpz;
                int ix1 = min(ix + 1, resm1), iy1 = min(iy + 1, resm1), iz1 = min(iz + 1, resm1);
                unsigned tx = half ? (unsigned)ix1 : (unsigned)ix;
                unsigned ay[2] = { (unsigned)iy * my, (unsigned)iy1 * my };
                unsigned az[2] = { (unsigned)iz * mz, (unsigned)iz1 * mz };
                float2 tv[4];
                #pragma unroll
                for (int j = 0; j < 4; ++j) {
                    int by = j >> 1, bz = j & 1;
                    unsigned idx = dense ? (tx + ay[by] + az[bz])
                                         : ((tx ^ ay[by] ^ az[bz]) & (unsigned)(TSZ - 1));
                    tv[j] = __ldg(tabl + idx);
                }
                float oy = 1.f - fy, oz = 1.f - fz;
                float S0 = 0.f, S1 = 0.f, Sy0 = 0.f, Sy1 = 0.f, Sz0 = 0.f, Sz1 = 0.f;
                #pragma unroll
                for (int j = 0; j < 4; ++j) {
                    int by = j >> 1, bz = j & 1;
                    float wy = by ? fy : oy, wz = bz ? fz : oz;
                    float wyz = wy * wz;
                    S0 = fmaf(tv[j].x, wyz, S0);  S1 = fmaf(tv[j].y, wyz, S1);
                    float syw = by ? wz : -wz;
                    Sy0 = fmaf(tv[j].x, syw, Sy0); Sy1 = fmaf(tv[j].y, syw, Sy1);
                    float szw = bz ? wy : -wy;
                    Sz0 = fmaf(tv[j].x, szw, Sz0); Sz1 = fmaf(tv[j].y, szw, Sz1);
                }
                float wxc = half ? fx : 1.f - fx;
                float So  = half ? S1 : S0,  Sp  = half ? S0 : S1;
                float Syo = half ? Sy1 : Sy0, Syp = half ? Sy0 : Sy1;
                float Szo = half ? Sz1 : Sz0, Szp = half ? Sz0 : Sz1;
                u64 A = __shfl_xor_sync(FULL, pk(wxc * Sp, sxsign * Sp), 1);
                u64 B = __shfl_xor_sync(FULL, pk(wxc * Syp, wxc * Szp), 1);
                float er, gxr, gyr, gzr;
                upk(A, er, gxr); upk(B, gyr, gzr);
                e2[q]  = fmaf(wxc, So, er);
                gx2[q] = (fmaf(sxsign, So, gxr)) * gscale;
                gy2[q] = (fmaf(wxc, Syo, gyr)) * gscale;
                gz2[q] = (fmaf(wxc, Szo, gzr)) * gscale;
            }
            encP[P] = pk(e2[0], e2[1]);
            dfw[(P * 3 + 0) * 32 + lane] = pk(gx2[0], gx2[1]);
            dfw[(P * 3 + 1) * 32 + lane] = pk(gy2[0], gy2[1]);
            dfw[(P * 3 + 2) * 32 + lane] = pk(gz2[0], gz2[1]);
        }

        // ---- prefetch x for NEXT iteration into the other buffer (coalesced) ----
        {
            int pnext = pbase + nwarp * (2 * NPAIR);
            if (pnext < NPTS) {
                long long base = (long long)pnext * 6;
                long long lim = (long long)NPTS * 6;
                float* dst = xbw + (((it + 1) & 1) * 64);
                if (base + lane < lim) dst[lane] = __ldg(x + base + lane);
                if (lane < 28 && base + 32 + lane < lim) dst[32 + lane] = __ldg(x + base + 32 + lane);
            }
        }

        // stage enc into activation ring
        __syncwarp();
        #pragma unroll
        for (int P = 0; P < NPAIR; ++P) abw[P * 64 + lane] = encP[P];
        __syncwarp();

        // ================= density layer0 (enc from smem broadcast) =================
        u64 h1[NPAIR][2];
        #pragma unroll
        for (int P = 0; P < NPAIR; ++P) { h1[P][0] = 0ull; h1[P][1] = 0ull; }
        #pragma unroll 4
        for (int i = 0; i < 16; ++i) {
            float4 w4 = ws0pk4[i * 32 + lane];
            u64 wx = bc2(w4.x), wy = bc2(w4.y), wz = bc2(w4.z), ww = bc2(w4.w);
            #pragma unroll
            for (int P = 0; P < NPAIR; ++P) {
                ulonglong2 e01 = *(const ulonglong2*)(abw + P * 64 + 2 * i);
                h1[P][0] = fma2(e01.x, wx, fma2(e01.y, wz, h1[P][0]));
                h1[P][1] = fma2(e01.x, wy, fma2(e01.y, ww, h1[P][1]));
            }
        }
        #pragma unroll
        for (int P = 0; P < NPAIR; ++P) { h1[P][0] = relu2(h1[P][0]); h1[P][1] = relu2(h1[P][1]); }

        // stage h1 into activation ring (overwrites enc)
        __syncwarp();
        #pragma unroll
        for (int P = 0; P < NPAIR; ++P) {
            abw[P * 64 + lane]      = h1[P][0];
            abw[P * 64 + 32 + lane] = h1[P][1];
        }
        __syncwarp();

        // ================= layer1: geo = h1 @ ws1 (pure fma2) =================
        u64 geo[NPAIR];
        #pragma unroll
        for (int P = 0; P < NPAIR; ++P) geo[P] = 0ull;
        #pragma unroll 2
        for (int i = 0; i < 16; ++i) {
            float4 w14 = ws1pk4[i * 16 + j16];
            u64 wA = bc2(w14.x), wB = bc2(w14.y), wC = bc2(w14.z), wD = bc2(w14.w);
            #pragma unroll
            for (int P = 0; P < NPAIR; ++P) {
                ulonglong2 a01 = *(const ulonglong2*)(abw + P * 64 + 2 * i);
                ulonglong2 b01 = *(const ulonglong2*)(abw + P * 64 + 32 + 2 * i);
                geo[P] = fma2(a01.x, wA, fma2(b01.x, wB, fma2(a01.y, wC, fma2(b01.y, wD, geo[P]))));
            }
        }

        // ================= dh per lane (owned k), overwrite ring with dh =================
        {
            float w10a = sws10[lane], w10b = sws10[lane + 32];
            __syncwarp();
            #pragma unroll
            for (int P = 0; P < NPAIR; ++P) {
                float a, b;
                upk(h1[P][0], a, b);
                abw[P * 64 + lane] = pk(a > 0.f ? w10a : 0.f, b > 0.f ? w10a : 0.f);
                upk(h1[P][1], a, b);
                abw[P * 64 + 32 + lane] = pk(a > 0.f ? w10b : 0.f, b > 0.f ? w10b : 0.f);
            }
            __syncwarp();
        }

        // ================= backward: genc = ws0t @ dh (pure fma2) =================
        u64 genc[NPAIR];
        #pragma unroll
        for (int P = 0; P < NPAIR; ++P) genc[P] = 0ull;
        #pragma unroll 2
        for (int i = 0; i < 16; ++i) {
            float4 wst = ws0tpk4[i * 32 + lane];
            u64 sA = bc2(wst.x), sB = bc2(wst.y), sC = bc2(wst.z), sD = bc2(wst.w);
            #pragma unroll
            for (int P = 0; P < NPAIR; ++P) {
                ulonglong2 a01 = *(const ulonglong2*)(abw + P * 64 + 2 * i);
                ulonglong2 b01 = *(const ulonglong2*)(abw + P * 64 + 32 + 2 * i);
                genc[P] = fma2(a01.x, sA, fma2(b01.x, sB, fma2(a01.y, sC, fma2(b01.y, sD, genc[P]))));
            }
        }

        // stage geo into activation ring (overwrites dh)
        __syncwarp();
        #pragma unroll
        for (int P = 0; P < NPAIR; ++P) abw[P * 64 + lane] = geo[P];
        __syncwarp();

        // ================= normal =================
        #pragma unroll
        for (int P = 0; P < NPAIR; ++P) {
            u64 sx = allsum2(mul2(genc[P], dfw[(P * 3 + 0) * 32 + lane]));
            u64 sy = allsum2(mul2(genc[P], dfw[(P * 3 + 1) * 32 + lane]));
            u64 sz = allsum2(mul2(genc[P], dfw[(P * 3 + 2) * 32 + lane]));
            float nx0, nx1, ny0, ny1, nz0, nz1;
            upk(sx, nx0, nx1); upk(sy, ny0, ny1); upk(sz, nz0, nz1);
            #pragma unroll
            for (int q = 0; q < 2; ++q) {
                int pidx = pbase + P * 2 + q;
                float n0 = -(q ? nx1 : nx0), n1 = -(q ? ny1 : ny0), n2 = -(q ? nz1 : nz0);
                float inv = 1.0f / fmaxf(sqrtf(n0 * n0 + n1 * n1 + n2 * n2), 1e-8f);
                if (lane < 3 && pidx < NPTS)
                    out[(size_t)NPTS * 16 + (size_t)pidx * 3 + lane] =
                        sel3(lane, n0 * inv, n1 * inv, n2 * inv);
            }
        }

        // ========== merged pred_normal (wn0) + mirror (wm0) broadcast loop ==========
        {
            u64 t0[NPAIR], t1[NPAIR], m[NPAIR];
            #pragma unroll
            for (int P = 0; P < NPAIR; ++P) { t0[P] = 0ull; t1[P] = 0ull; m[P] = bc2(sbm0[lane]); }
            #pragma unroll
            for (int ii = 0; ii < 8; ++ii) {
                float4 w4 = wn0pk4[ii * 32 + lane];
                float2 w2 = wm0pk2[ii * 32 + lane];
                u64 wx = bc2(w4.x), wy = bc2(w4.y), wz = bc2(w4.z), ww = bc2(w4.w);
                u64 mx = bc2(w2.x), mzx = bc2(w2.y);
                #pragma unroll
                for (int P = 0; P < NPAIR; ++P) {
                    u64 g1 = abw[P * 64 + 2 * ii + 1];
                    u64 g2 = abw[P * 64 + 2 * ii + 2];
                    t0[P] = fma2(g1, wx, fma2(g2, wz, t0[P]));
                    t1[P] = fma2(g1, wy, fma2(g2, ww, t1[P]));
                    m[P]  = fma2(g1, mx, fma2(g2, mzx, m[P]));
                }
            }
            #pragma unroll
            for (int P = 0; P < NPAIR; ++P) { t0[P] = relu2(t0[P]); t1[P] = relu2(t1[P]); }
            #pragma unroll
            for (int P = 0; P < NPAIR; ++P) {
                float pn[3][2];
                #pragma unroll
                for (int d = 0; d < 3; ++d) {
                    u64 wA = bc2(swn1[lane * 3 + d]);
                    u64 wB = bc2(swn1[(lane + 32) * 3 + d]);
                    u64 s = allsum2(fma2(t0[P], wA, mul2(t1[P], wB)));
                    upk(s, pn[d][0], pn[d][1]);
                }
                #pragma unroll
                for (int q = 0; q < 2; ++q) {
                    int pidx = pbase + P * 2 + q;
                    float n0 = pn[0][q], n1 = pn[1][q], n2 = pn[2][q];
                    float inv = 1.0f / fmaxf(sqrtf(n0 * n0 + n1 * n1 + n2 * n2), 1e-8f);
                    if (lane < 3 && pidx < NPTS)
                        out[(size_t)NPTS * 19 + (size_t)pidx * 3 + lane] =
                            sel3(lane, n0 * inv, n1 * inv, n2 * inv);
                }
            }
            // mirror leaky-relu + reduction + store
            float bm1v = smem[OFF_BM1];
            u64 wv = bc2(swm1[lane]);
            #pragma unroll
            for (int P = 0; P < NPAIR; ++P) {
                float a, b; upk(m[P], a, b);
                a = a > 0.f ? a : 0.01f * a;
                b = b > 0.f ? b : 0.01f * b;
                u64 s = allsum2(mul2(pk(a, b), wv));
                float s0, s1; upk(s, s0, s1);
                if (lane == 0) {
                    int p0 = pbase + P * 2;
                    if (p0 < NPTS)     out[(size_t)NPTS * 25 + p0]     = sigm(s0 + bm1v);
                    if (p0 + 1 < NPTS) out[(size_t)NPTS * 25 + p0 + 1] = sigm(s1 + bm1v);
                }
            }
        }

        // ================= sigma + geo_feat (geo read from ring) =================
        #pragma unroll
        for (int P = 0; P < NPAIR; ++P) {
            u64 g = abw[P * 64 + lane];
            float gA, gB; upk(g, gA, gB);
            int p0 = pbase + P * 2, p1 = p0 + 1;
            if (lane == 0) {
                if (p0 < NPTS) out[p0] = gA;
                if (p1 < NPTS) out[p1] = gB;
            }
            if (lane >= 1 && lane < 16) {
                if (p0 < NPTS) out[(size_t)NPTS + (size_t)p0 * 15 + (lane - 1)] = gA;
                if (p1 < NPTS) out[(size_t)NPTS + (size_t)p1 * 15 + (lane - 1)] = gB;
            }
        }

        // ================= color =================
        {
            u64 ca[NPAIR], cb[NPAIR];
            #pragma unroll
            for (int P = 0; P < NPAIR; ++P) { ca[P] = 0ull; cb[P] = 0ull; }
            #pragma unroll
            for (int ii = 0; ii < 8; ++ii) {
                float4 w4 = wc0ge4[ii * 32 + lane];
                u64 wx = bc2(w4.x), wy = bc2(w4.y), wz = bc2(w4.z), ww = bc2(w4.w);
                #pragma unroll
                for (int P = 0; P < NPAIR; ++P) {
                    u64 g1 = abw[P * 64 + 2 * ii + 1];
                    u64 g2 = abw[P * 64 + 2 * ii + 2];
                    ca[P] = fma2(g1, wx, fma2(g2, wz, ca[P]));
                    cb[P] = fma2(g1, wy, fma2(g2, ww, cb[P]));
                }
            }
            #pragma unroll
            for (int P = 0; P < NPAIR; ++P) {
                const float* x0 = xc + (2 * P) * 6;
                const float* x1 = xc + (2 * P + 1) * 6;
                u64 X = pk(x0[3], x1[3]);
                u64 Y = pk(x0[4], x1[4]);
                u64 Z = pk(x0[5], x1[5]);
                u64 XY = mul2(X, Y), XZ = mul2(X, Z), YZ = mul2(Y, Z);
                u64 X2 = mul2(X, X), Y2 = mul2(Y, Y), Z2 = mul2(Z, Z);
                u64 a = ca[P], b = cb[P];
                #define ACC2(ii, e0, e1) { u64 s0_ = (e0), s1_ = (e1); float4 w_ = wc0sh4[(ii) * 32 + lane]; \
                    a = fma2(s0_, bc2(w_.x), fma2(s1_, bc2(w_.z), a)); \
                    b = fma2(s0_, bc2(w_.y), fma2(s1_, bc2(w_.w), b)); }
                ACC2(0, bc2(0.28209479177387814f),
                        mul2(bc2(-0.48860251190291987f), Y));
                ACC2(1, mul2(bc2(0.48860251190291987f), Z),
                        mul2(bc2(-0.48860251190291987f), X));
                ACC2(2, mul2(bc2(1.0925484305920792f), XY),
                        mul2(bc2(-1.0925484305920792f), YZ));
                ACC2(3, fma2(bc2(0.94617469575756f), Z2, bc2(-0.31539156525252005f)),
                        mul2(bc2(-1.0925484305920792f), XZ));
                ACC2(4, mul2(bc2(0.5462742152960396f), fma2(Y2, bc2(-1.f), X2)),
                        mul2(bc2(0.5900435899266435f), mul2(Y, fma2(bc2(-3.f), X2, Y2))));
                ACC2(5, mul2(bc2(2.890611442640554f), mul2(XY, Z)),
                        mul2(bc2(0.4570457994644657f), mul2(Y, fma2(bc2(-5.f), Z2, bc2(1.f)))));
                ACC2(6, mul2(bc2(0.3731763325901154f), mul2(Z, fma2(bc2(5.f), Z2, bc2(-3.f)))),
                        mul2(bc2(0.4570457994644657f), mul2(X, fma2(bc2(-5.f), Z2, bc2(1.f)))));
                ACC2(7, mul2(bc2(1.445305721320277f), mul2(Z, fma2(Y2, bc2(-1.f), X2))),
                        mul2(bc2(0.5900435899266435f), mul2(X, fma2(bc2(-3.f), Y2, X2))));
                #undef ACC2
                ca[P] = relu2(a); cb[P] = relu2(b);
            }
            // stage ca/cb into ring (overwrites geo slots; geo no longer needed)
            __syncwarp();
            #pragma unroll
            for (int P = 0; P < NPAIR; ++P) {
                abw[P * 64 + 2 * lane]     = ca[P];
                abw[P * 64 + 2 * lane + 1] = cb[P];
            }
            __syncwarp();
            u64 c10[NPAIR], c11[NPAIR];
            #pragma unroll
            for (int P = 0; P < NPAIR; ++P) { c10[P] = 0ull; c11[P] = 0ull; }
            #pragma unroll 2
            for (int kk = 0; kk < 32; ++kk) {
                float4 w4 = wc1pk[kk * 32 + lane];
                u64 w00 = bc2(w4.x), w01 = bc2(w4.y), w10 = bc2(w4.z), w11 = bc2(w4.w);
                #pragma unroll
                for (int P = 0; P < NPAIR; ++P) {
                    ulonglong2 hab = *(const ulonglong2*)(abw + P * 64 + 2 * kk);
                    c10[P] = fma2(hab.x, w00, fma2(hab.y, w10, c10[P]));
                    c11[P] = fma2(hab.x, w01, fma2(hab.y, w11, c11[P]));
                }
            }
            #pragma unroll
            for (int P = 0; P < NPAIR; ++P) { c10[P] = relu2(c10[P]); c11[P] = relu2(c11[P]); }
            #pragma unroll
            for (int d = 0; d < 3; ++d) {
                u64 wA = bc2(swc2[lane * 3 + d]);
                u64 wB = bc2(swc2[(lane + 32) * 3 + d]);
                #pragma unroll
                for (int P = 0; P < NPAIR; ++P) {
                    u64 s = allsum2(fma2(c10[P], wA, mul2(c11[P], wB)));
                    float r0, r1; upk(s, r0, r1);
                    if (lane == d) {
                        int p0 = pbase + P * 2;
                        if (p0 < NPTS)     out[(size_t)NPTS * 22 + (size_t)p0 * 3 + d]       = sigm(r0);
                        if (p0 + 1 < NPTS) out[(size_t)NPTS * 22 + (size_t)(p0 + 1) * 3 + d] = sigm(r1);
                    }
                }
            }
        }
        __syncwarp();
    }
}

extern "C" void kernel_launch(void* const* d_in, const int* in_sizes, int n_in,
                              void* d_out, int out_size) {
    (void)in_sizes; (void)n_in; (void)out_size;
    HGParams prm;
    double pls = exp2(log2(2048.0 * 1.0 / 16.0) / 15.0);
    for (int l = 0; l < 16; ++l) {
        int r = (int)floor(16.0 * pow(pls, (double)l));
        prm.res[l] = r;
        long long r3 = (long long)r * r * r;
        prm.dense[l] = (r3 <= (long long)TSZ) ? 1 : 0;
    }
    size_t smemBytes = (size_t)SMEM_FLOATS * sizeof(float);
    cudaFuncSetAttribute(nerf_kernel, cudaFuncAttributeMaxDynamicSharedMemorySize, (int)smemBytes);
    nerf_kernel<<<NBLOCKS, NTHREADS, smemBytes>>>(
        (const float*)d_in[0], (const float*)d_in[1],
        (const float*)d_in[2], (const float*)d_in[3],
        (const float*)d_in[4], (const float*)d_in[5], (const float*)d_in[6],
        (const float*)d_in[7], (const float*)d_in[8],
        (const float*)d_in[9], (const float*)d_in[10],
        (const float*)d_in[11], (const float*)d_in[12],
        (float*)d_out, prm);
}

// round 15
// speedup vs baseline: 1.1316x; 1.1316x over previous
#include <cuda_runtime.h>
#include <math.h>
#include <stdint.h>

#define NPTS 524288
#define TSZ  524288
#define NTHREADS 256
#define NWARPS_BLK 8
#define NBLOCKS 296
#define FULL 0xffffffffu
#define NPAIR 4   // 8 points per warp iteration

typedef unsigned long long u64;

// ---- shared memory layout (float offsets) ----
#define OFF_WS0PK4  0       // [16][32] float4
#define OFF_WS0TPK4 2048    // [16][32] float4
#define OFF_WS1PK4  4096    // [16][16] float4
#define OFF_WC1PK   5120    // [32][32] float4
#define OFF_WC0SH4  9216    // [8][32] float4
#define OFF_WC0GE4  10240   // [8][32] float4
#define OFF_WN0PK4  11264   // [8][32] float4
#define OFF_WM0PK2  12288   // [8][32] float2
#define OFF_WC2     12800   // [64][3]
#define OFF_WN1     12992   // [64][3]
#define OFF_WM1     13184   // [32]
#define OFF_BM0     13216   // [32]
#define OFF_BM1     13248   // [1]
#define OFF_WS10    13250   // [64] ws1 column 0
#define OFF_DF      13316   // 8 warps * 384 u64 = 6144 floats
#define OFF_ABUF    19460   // 8 warps * 256 u64 = 4096 floats (16B aligned)
#define OFF_XBUF    23556   // 8 warps * 128 floats (2 buffers x 64)
#define SMEM_FLOATS 24580

struct HGParams { int res[16]; int dense[16]; };

__device__ __forceinline__ u64 pk(float lo, float hi) {
    u64 r; asm("mov.b64 %0,{%1,%2};" : "=l"(r) : "f"(lo), "f"(hi)); return r;
}
__device__ __forceinline__ void upk(u64 v, float& lo, float& hi) {
    asm("mov.b64 {%0,%1},%2;" : "=f"(lo), "=f"(hi) : "l"(v));
}
__device__ __forceinline__ u64 bc2(float w) { return pk(w, w); }
__device__ __forceinline__ u64 fma2(u64 a, u64 b, u64 c) {
    u64 d; asm("fma.rn.f32x2 %0,%1,%2,%3;" : "=l"(d) : "l"(a), "l"(b), "l"(c)); return d;
}
__device__ __forceinline__ u64 mul2(u64 a, u64 b) {
    u64 d; asm("mul.rn.f32x2 %0,%1,%2;" : "=l"(d) : "l"(a), "l"(b)); return d;
}
__device__ __forceinline__ u64 add2(u64 a, u64 b) {
    u64 d; asm("add.rn.f32x2 %0,%1,%2;" : "=l"(d) : "l"(a), "l"(b)); return d;
}
__device__ __forceinline__ u64 relu2(u64 v) {
    float a, b; upk(v, a, b); return pk(fmaxf(a, 0.f), fmaxf(b, 0.f));
}
__device__ __forceinline__ u64 allsum2(u64 v) {
    #pragma unroll
    for (int o = 16; o > 0; o >>= 1) v = add2(v, __shfl_xor_sync(FULL, v, o));
    return v;
}
__device__ __forceinline__ float sigm(float v) { return 1.0f / (1.0f + expf(-v)); }
__device__ __forceinline__ float sel3(int lane, float a, float b, float c) {
    return lane == 0 ? a : (lane == 1 ? b : c);
}

extern __shared__ float smem[];

__global__ __launch_bounds__(NTHREADS, 2) void nerf_kernel(
    const float* __restrict__ x,
    const float* __restrict__ tables,
    const float* __restrict__ ws0, const float* __restrict__ ws1,
    const float* __restrict__ wc0, const float* __restrict__ wc1, const float* __restrict__ wc2,
    const float* __restrict__ wn0, const float* __restrict__ wn1,
    const float* __restrict__ wm0, const float* __restrict__ bm0,
    const float* __restrict__ wm1, const float* __restrict__ bm1,
    float* __restrict__ out, HGParams prm)
{
    const int tid = threadIdx.x;
    {
        float4* p0 = (float4*)(smem + OFF_WS0PK4);
        for (int i = tid; i < 512; i += NTHREADS) { int r = i >> 5, c = i & 31;
            p0[i] = make_float4(ws0[(2*r)*64+c], ws0[(2*r)*64+c+32], ws0[(2*r+1)*64+c], ws0[(2*r+1)*64+c+32]); }
        float4* pt4 = (float4*)(smem + OFF_WS0TPK4);
        for (int i = tid; i < 512; i += NTHREADS) { int r = i >> 5, c = i & 31;
            pt4[i] = make_float4(ws0[c*64+2*r], ws0[c*64+2*r+32], ws0[c*64+2*r+1], ws0[c*64+2*r+1+32]); }
        float4* p14 = (float4*)(smem + OFF_WS1PK4);
        for (int i = tid; i < 256; i += NTHREADS) { int r = i >> 4, j = i & 15;
            p14[i] = make_float4(ws1[(2*r)*16+j], ws1[(2*r+32)*16+j], ws1[(2*r+1)*16+j], ws1[(2*r+1+32)*16+j]); }
        float4* pc1 = (float4*)(smem + OFF_WC1PK);
        for (int i = tid; i < 1024; i += NTHREADS) { int kk = i >> 5, c = i & 31;
            pc1[i] = make_float4(wc1[kk*64+c], wc1[kk*64+c+32], wc1[(kk+32)*64+c], wc1[(kk+32)*64+c+32]); }
        float4* psh = (float4*)(smem + OFF_WC0SH4);
        for (int i = tid; i < 256; i += NTHREADS) { int r = i >> 5, c = i & 31;
            psh[i] = make_float4(wc0[(2*r)*64+c], wc0[(2*r)*64+c+32], wc0[(2*r+1)*64+c], wc0[(2*r+1)*64+c+32]); }
        float4* pge = (float4*)(smem + OFF_WC0GE4);
        for (int i = tid; i < 256; i += NTHREADS) { int r = i >> 5, c = i & 31;
            int r0 = 16 + 2*r, r1 = 17 + 2*r;
            float w2 = (r1 <= 30) ? wc0[r1*64+c] : 0.f;
            float w3 = (r1 <= 30) ? wc0[r1*64+c+32] : 0.f;
            pge[i] = make_float4(wc0[r0*64+c], wc0[r0*64+c+32], w2, w3); }
        float4* pn4 = (float4*)(smem + OFF_WN0PK4);
        for (int i = tid; i < 256; i += NTHREADS) { int r = i >> 5, c = i & 31;
            int r1 = 2*r+1;
            float w2 = (r1 <= 14) ? wn0[r1*64+c] : 0.f;
            float w3 = (r1 <= 14) ? wn0[r1*64+c+32] : 0.f;
            pn4[i] = make_float4(wn0[(2*r)*64+c], wn0[(2*r)*64+c+32], w2, w3); }
        float2* pm2 = (float2*)(smem + OFF_WM0PK2);
        for (int i = tid; i < 256; i += NTHREADS) { int r = i >> 5, c = i & 31;
            int r1 = 2*r+1;
            float w1 = (r1 <= 14) ? wm0[r1*32+c] : 0.f;
            pm2[i] = make_float2(wm0[(2*r)*32+c], w1); }
        for (int i = tid; i < 192; i += NTHREADS) smem[OFF_WC2 + i] = wc2[i];
        for (int i = tid; i < 192; i += NTHREADS) smem[OFF_WN1 + i] = wn1[i];
        for (int i = tid; i < 32;  i += NTHREADS) smem[OFF_WM1 + i] = wm1[i];
        for (int i = tid; i < 32;  i += NTHREADS) smem[OFF_BM0 + i] = bm0[i];
        for (int i = tid; i < 64;  i += NTHREADS) smem[OFF_WS10 + i] = ws1[i * 16];
        if (tid == 0) smem[OFF_BM1] = bm1[0];
    }
    __syncthreads();

    const int lane = tid & 31;
    const int warpInBlk = tid >> 5;
    const int gwarp = blockIdx.x * NWARPS_BLK + warpInBlk;
    const int nwarp = gridDim.x * NWARPS_BLK;
    const int j16 = lane & 15;

    const int lvl = lane >> 1;
    const int half = lane & 1;
    const float sxsign = half ? 1.f : -1.f;
    const int res = prm.res[lvl];
    const int dense = prm.dense[lvl];
    const int resm1 = res - 1;
    const float rm1 = (float)resm1;
    const float gscale = rm1 * 0.5f;
    const unsigned my = dense ? (unsigned)res : 2654435761u;
    const unsigned mz = dense ? (unsigned)(res * res) : 805459861u;
    const float2* __restrict__ tabl = ((const float2*)tables) + (size_t)lvl * TSZ;

    const float4* ws0pk4  = (const float4*)(smem + OFF_WS0PK4);
    const float4* ws0tpk4 = (const float4*)(smem + OFF_WS0TPK4);
    const float4* ws1pk4  = (const float4*)(smem + OFF_WS1PK4);
    const float4* wc1pk   = (const float4*)(smem + OFF_WC1PK);
    const float4* wc0sh4  = (const float4*)(smem + OFF_WC0SH4);
    const float4* wc0ge4  = (const float4*)(smem + OFF_WC0GE4);
    const float4* wn0pk4  = (const float4*)(smem + OFF_WN0PK4);
    const float2* wm0pk2  = (const float2*)(smem + OFF_WM0PK2);
    const float* swc2 = smem + OFF_WC2;
    const float* swn1 = smem + OFF_WN1;
    const float* swm1 = smem + OFF_WM1;
    const float* sbm0 = smem + OFF_BM0;
    const float* sws10 = smem + OFF_WS10;
    u64* dfw  = ((u64*)(smem + OFF_DF))  + warpInBlk * (NPAIR * 3 * 32);
    u64* abw  = ((u64*)(smem + OFF_ABUF)) + warpInBlk * 256;   // 64 u64 per P
    float* xbw = smem + OFF_XBUF + warpInBlk * 128;            // 2 buffers x 64 floats

    // ---- prologue: prefetch x for first iteration into buffer 0 ----
    {
        int p0 = gwarp * (2 * NPAIR);
        if (p0 < NPTS) {
            const float* src = x + (size_t)p0 * 6;
            xbw[lane] = __ldg(src + lane);
            if (lane < 16) xbw[32 + lane] = __ldg(src + 32 + lane);
        }
    }
    __syncwarp();

    int it = 0;
    for (int pbase = gwarp * (2 * NPAIR); pbase < NPTS; pbase += nwarp * (2 * NPAIR), ++it) {
        const float* xc = xbw + ((it & 1) * 64);

        // ================= hashgrid gather (x from smem buffer) =================
        u64 encP[NPAIR];
        #pragma unroll
        for (int P = 0; P < NPAIR; ++P) {
            float e2[2], gx2[2], gy2[2], gz2[2];
            #pragma unroll
            for (int q = 0; q < 2; ++q) {
                const float* xp = xc + (2 * P + q) * 6;
                float X = fminf(fmaxf((xp[0] + 1.0f) * 0.5f, 0.0f), 1.0f);
                float Y = fminf(fmaxf((xp[1] + 1.0f) * 0.5f, 0.0f), 1.0f);
                float Z = fminf(fmaxf((xp[2] + 1.0f) * 0.5f, 0.0f), 1.0f);
                float px = X * rm1, py = Y * rm1, pz = Z * rm1;
                float fpx = floorf(px), fpy = floorf(py), fpz = floorf(pz);
                float fx = px - fpx, fy = py - fpy, fz = pz - fpz;
                int ix = (int)fpx, iy = (int)fpy, iz = (int)fpz;
                int ix1 = min(ix + 1, resm1), iy1 = min(iy + 1, resm1), iz1 = min(iz + 1, resm1);
                unsigned tx = half ? (unsigned)ix1 : (unsigned)ix;
                unsigned ay[2] = { (unsigned)iy * my, (unsigned)iy1 * my };
                unsigned az[2] = { (unsigned)iz * mz, (unsigned)iz1 * mz };
                float2 tv[4];
                #pragma unroll
                for (int j = 0; j < 4; ++j) {
                    int by = j >> 1, bz = j & 1;
                    unsigned idx = dense ? (tx + ay[by] + az[bz])
                                         : ((tx ^ ay[by] ^ az[bz]) & (unsigned)(TSZ - 1));
                    tv[j] = __ldg(tabl + idx);
                }
                float oy = 1.f - fy, oz = 1.f - fz;
                float S0 = 0.f, S1 = 0.f, Sy0 = 0.f, Sy1 = 0.f, Sz0 = 0.f, Sz1 = 0.f;
                #pragma unroll
                for (int j = 0; j < 4; ++j) {
                    int by = j >> 1, bz = j & 1;
                    float wy = by ? fy : oy, wz = bz ? fz : oz;
                    float wyz = wy * wz;
                    S0 = fmaf(tv[j].x, wyz, S0);  S1 = fmaf(tv[j].y, wyz, S1);
                    float syw = by ? wz : -wz;
                    Sy0 = fmaf(tv[j].x, syw, Sy0); Sy1 = fmaf(tv[j].y, syw, Sy1);
                    float szw = bz ? wy : -wy;
                    Sz0 = fmaf(tv[j].x, szw, Sz0); Sz1 = fmaf(tv[j].y, szw, Sz1);
                }
                float wxc = half ? fx : 1.f - fx;
                float So  = half ? S1 : S0,  Sp  = half ? S0 : S1;
                float Syo = half ? Sy1 : Sy0, Syp = half ? Sy0 : Sy1;
                float Szo = half ? Sz1 : Sz0, Szp = half ? Sz0 : Sz1;
                u64 A = __shfl_xor_sync(FULL, pk(wxc * Sp, sxsign * Sp), 1);
                u64 B = __shfl_xor_sync(FULL, pk(wxc * Syp, wxc * Szp), 1);
                float er, gxr, gyr, gzr;
                upk(A, er, gxr); upk(B, gyr, gzr);
                e2[q]  = fmaf(wxc, So, er);
                gx2[q] = (fmaf(sxsign, So, gxr)) * gscale;
                gy2[q] = (fmaf(wxc, Syo, gyr)) * gscale;
                gz2[q] = (fmaf(wxc, Szo, gzr)) * gscale;
            }
            encP[P] = pk(e2[0], e2[1]);
            dfw[(P * 3 + 0) * 32 + lane] = pk(gx2[0], gx2[1]);
            dfw[(P * 3 + 1) * 32 + lane] = pk(gy2[0], gy2[1]);
            dfw[(P * 3 + 2) * 32 + lane] = pk(gz2[0], gz2[1]);
        }

        // ---- prefetch x for NEXT iteration into the other buffer (coalesced) ----
        {
            int pnext = pbase + nwarp * (2 * NPAIR);
            if (pnext < NPTS) {
                const float* src = x + (size_t)pnext * 6;
                float* dst = xbw + (((it + 1) & 1) * 64);
                dst[lane] = __ldg(src + lane);
                if (lane < 16) dst[32 + lane] = __ldg(src + 32 + lane);
            }
        }

        // stage enc into activation ring
        __syncwarp();
        #pragma unroll
        for (int P = 0; P < NPAIR; ++P) abw[P * 64 + lane] = encP[P];
        __syncwarp();

        // ================= density layer0 (enc from smem broadcast) =================
        u64 h1[NPAIR][2];
        #pragma unroll
        for (int P = 0; P < NPAIR; ++P) { h1[P][0] = 0ull; h1[P][1] = 0ull; }
        #pragma unroll 4
        for (int i = 0; i < 16; ++i) {
            float4 w4 = ws0pk4[i * 32 + lane];
            u64 wx = bc2(w4.x), wy = bc2(w4.y), wz = bc2(w4.z), ww = bc2(w4.w);
            #pragma unroll
            for (int P = 0; P < NPAIR; ++P) {
                ulonglong2 e01 = *(const ulonglong2*)(abw + P * 64 + 2 * i);
                h1[P][0] = fma2(e01.x, wx, fma2(e01.y, wz, h1[P][0]));
                h1[P][1] = fma2(e01.x, wy, fma2(e01.y, ww, h1[P][1]));
            }
        }
        #pragma unroll
        for (int P = 0; P < NPAIR; ++P) { h1[P][0] = relu2(h1[P][0]); h1[P][1] = relu2(h1[P][1]); }

        // stage h1 into activation ring (overwrites enc)
        __syncwarp();
        #pragma unroll
        for (int P = 0; P < NPAIR; ++P) {
            abw[P * 64 + lane]      = h1[P][0];
            abw[P * 64 + 32 + lane] = h1[P][1];
        }
        __syncwarp();

        // ================= layer1: geo = h1 @ ws1 (pure fma2) =================
        u64 geo[NPAIR];
        #pragma unroll
        for (int P = 0; P < NPAIR; ++P) geo[P] = 0ull;
        #pragma unroll 2
        for (int i = 0; i < 16; ++i) {
            float4 w14 = ws1pk4[i * 16 + j16];
            u64 wA = bc2(w14.x), wB = bc2(w14.y), wC = bc2(w14.z), wD = bc2(w14.w);
            #pragma unroll
            for (int P = 0; P < NPAIR; ++P) {
                ulonglong2 a01 = *(const ulonglong2*)(abw + P * 64 + 2 * i);
                ulonglong2 b01 = *(const ulonglong2*)(abw + P * 64 + 32 + 2 * i);
                geo[P] = fma2(a01.x, wA, fma2(b01.x, wB, fma2(a01.y, wC, fma2(b01.y, wD, geo[P]))));
            }
        }

        // ================= dh per lane (owned k), overwrite ring with dh =================
        {
            float w10a = sws10[lane], w10b = sws10[lane + 32];
            __syncwarp();
            #pragma unroll
            for (int P = 0; P < NPAIR; ++P) {
                float a, b;
                upk(h1[P][0], a, b);
                abw[P * 64 + lane] = pk(a > 0.f ? w10a : 0.f, b > 0.f ? w10a : 0.f);
                upk(h1[P][1], a, b);
                abw[P * 64 + 32 + lane] = pk(a > 0.f ? w10b : 0.f, b > 0.f ? w10b : 0.f);
            }
            __syncwarp();
        }

        // ================= backward: genc = ws0t @ dh (pure fma2) =================
        u64 genc[NPAIR];
        #pragma unroll
        for (int P = 0; P < NPAIR; ++P) genc[P] = 0ull;
        #pragma unroll 2
        for (int i = 0; i < 16; ++i) {
            float4 wst = ws0tpk4[i * 32 + lane];
            u64 sA = bc2(wst.x), sB = bc2(wst.y), sC = bc2(wst.z), sD = bc2(wst.w);
            #pragma unroll
            for (int P = 0; P < NPAIR; ++P) {
                ulonglong2 a01 = *(const ulonglong2*)(abw + P * 64 + 2 * i);
                ulonglong2 b01 = *(const ulonglong2*)(abw + P * 64 + 32 + 2 * i);
                genc[P] = fma2(a01.x, sA, fma2(b01.x, sB, fma2(a01.y, sC, fma2(b01.y, sD, genc[P]))));
            }
        }

        // stage geo into activation ring (overwrites dh)
        __syncwarp();
        #pragma unroll
        for (int P = 0; P < NPAIR; ++P) abw[P * 64 + lane] = geo[P];
        __syncwarp();

        // ================= normal =================
        #pragma unroll
        for (int P = 0; P < NPAIR; ++P) {
            u64 sx = allsum2(mul2(genc[P], dfw[(P * 3 + 0) * 32 + lane]));
            u64 sy = allsum2(mul2(genc[P], dfw[(P * 3 + 1) * 32 + lane]));
            u64 sz = allsum2(mul2(genc[P], dfw[(P * 3 + 2) * 32 + lane]));
            float nx0, nx1, ny0, ny1, nz0, nz1;
            upk(sx, nx0, nx1); upk(sy, ny0, ny1); upk(sz, nz0, nz1);
            #pragma unroll
            for (int q = 0; q < 2; ++q) {
                float n0 = -(q ? nx1 : nx0), n1 = -(q ? ny1 : ny0), n2 = -(q ? nz1 : nz0);
                float inv = 1.0f / fmaxf(sqrtf(n0 * n0 + n1 * n1 + n2 * n2), 1e-8f);
                if (lane < 3)
                    out[(size_t)NPTS * 16 + (size_t)(pbase + P * 2 + q) * 3 + lane] =
                        sel3(lane, n0 * inv, n1 * inv, n2 * inv);
            }
        }

        // ========== merged pred_normal (wn0) + mirror (wm0) broadcast loop ==========
        {
            u64 t0[NPAIR], t1[NPAIR], m[NPAIR];
            #pragma unroll
            for (int P = 0; P < NPAIR; ++P) { t0[P] = 0ull; t1[P] = 0ull; m[P] = bc2(sbm0[lane]); }
            #pragma unroll
            for (int ii = 0; ii < 8; ++ii) {
                float4 w4 = wn0pk4[ii * 32 + lane];
                float2 w2 = wm0pk2[ii * 32 + lane];
                u64 wx = bc2(w4.x), wy = bc2(w4.y), wz = bc2(w4.z), ww = bc2(w4.w);
                u64 mx = bc2(w2.x), mzx = bc2(w2.y);
                #pragma unroll
                for (int P = 0; P < NPAIR; ++P) {
                    u64 g1 = abw[P * 64 + 2 * ii + 1];
                    u64 g2 = abw[P * 64 + 2 * ii + 2];
                    t0[P] = fma2(g1, wx, fma2(g2, wz, t0[P]));
                    t1[P] = fma2(g1, wy, fma2(g2, ww, t1[P]));
                    m[P]  = fma2(g1, mx, fma2(g2, mzx, m[P]));
                }
            }
            // pred_normal reductions + store
            #pragma unroll
            for (int P = 0; P < NPAIR; ++P) { t0[P] = relu2(t0[P]); t1[P] = relu2(t1[P]); }
            #pragma unroll
            for (int P = 0; P < NPAIR; ++P) {
                float pn[3][2];
                #pragma unroll
                for (int d = 0; d < 3; ++d) {
                    u64 wA = bc2(swn1[lane * 3 + d]);
                    u64 wB = bc2(swn1[(lane + 32) * 3 + d]);
                    u64 s = allsum2(fma2(t0[P], wA, mul2(t1[P], wB)));
                    upk(s, pn[d][0], pn[d][1]);
                }
                #pragma unroll
                for (int q = 0; q < 2; ++q) {
                    float n0 = pn[0][q], n1 = pn[1][q], n2 = pn[2][q];
                    float inv = 1.0f / fmaxf(sqrtf(n0 * n0 + n1 * n1 + n2 * n2), 1e-8f);
                    if (lane < 3)
                        out[(size_t)NPTS * 19 + (size_t)(pbase + P * 2 + q) * 3 + lane] =
                            sel3(lane, n0 * inv, n1 * inv, n2 * inv);
                }
            }
            // mirror leaky-relu + reduction + store
            float bm1v = smem[OFF_BM1];
            u64 wv = bc2(swm1[lane]);
            #pragma unroll
            for (int P = 0; P < NPAIR; ++P) {
                float a, b; upk(m[P], a, b);
                a = a > 0.f ? a : 0.01f * a;
                b = b > 0.f ? b : 0.01f * b;
                u64 s = allsum2(mul2(pk(a, b), wv));
                float s0, s1; upk(s, s0, s1);
                if (lane == 0) {
                    out[(size_t)NPTS * 25 + (pbase + P * 2 + 0)] = sigm(s0 + bm1v);
                    out[(size_t)NPTS * 25 + (pbase + P * 2 + 1)] = sigm(s1 + bm1v);
                }
            }
        }

        // ================= sigma (coalesced, from ring slot 0) + geo_feat =================
        if (lane < 2 * NPAIR) {
            u64 g = abw[(lane >> 1) * 64];
            float gA, gB; upk(g, gA, gB);
            out[(size_t)(pbase + lane)] = (lane & 1) ? gB : gA;
        }
        #pragma unroll
        for (int P = 0; P < NPAIR; ++P) {
            float gA, gB; upk(geo[P], gA, gB);
            size_t p0 = (size_t)(pbase + P * 2), p1 = p0 + 1;
            if (lane >= 1 && lane < 16) {
                out[(size_t)NPTS + p0 * 15 + (lane - 1)] = gA;
                out[(size_t)NPTS + p1 * 15 + (lane - 1)] = gB;
            }
        }

        // ================= color =================
        {
            u64 ca[NPAIR], cb[NPAIR];
            #pragma unroll
            for (int P = 0; P < NPAIR; ++P) { ca[P] = 0ull; cb[P] = 0ull; }
            // geo part (geo from smem ring)
            #pragma unroll
            for (int ii = 0; ii < 8; ++ii) {
                float4 w4 = wc0ge4[ii * 32 + lane];
                u64 wx = bc2(w4.x), wy = bc2(w4.y), wz = bc2(w4.z), ww = bc2(w4.w);
                #pragma unroll
                for (int P = 0; P < NPAIR; ++P) {
                    u64 g1 = abw[P * 64 + 2 * ii + 1];
                    u64 g2 = abw[P * 64 + 2 * ii + 2];
                    ca[P] = fma2(g1, wx, fma2(g2, wz, ca[P]));
                    cb[P] = fma2(g1, wy, fma2(g2, ww, cb[P]));
                }
            }
            // SH part, dir straight from the x buffer
            #pragma unroll
            for (int P = 0; P < NPAIR; ++P) {
                const float* x0 = xc + (2 * P) * 6;
                const float* x1 = xc + (2 * P + 1) * 6;
                u64 X = pk(x0[3], x1[3]);
                u64 Y = pk(x0[4], x1[4]);
                u64 Z = pk(x0[5], x1[5]);
                u64 XY = mul2(X, Y), XZ = mul2(X, Z), YZ = mul2(Y, Z);
                u64 X2 = mul2(X, X), Y2 = mul2(Y, Y), Z2 = mul2(Z, Z);
                u64 a = ca[P], b = cb[P];
                #define ACC2(ii, e0, e1) { u64 s0_ = (e0), s1_ = (e1); float4 w_ = wc0sh4[(ii) * 32 + lane]; \
                    a = fma2(s0_, bc2(w_.x), fma2(s1_, bc2(w_.z), a)); \
                    b = fma2(s0_, bc2(w_.y), fma2(s1_, bc2(w_.w), b)); }
                ACC2(0, bc2(0.28209479177387814f),
                        mul2(bc2(-0.48860251190291987f), Y));
                ACC2(1, mul2(bc2(0.48860251190291987f), Z),
                        mul2(bc2(-0.48860251190291987f), X));
                ACC2(2, mul2(bc2(1.0925484305920792f), XY),
                        mul2(bc2(-1.0925484305920792f), YZ));
                ACC2(3, fma2(bc2(0.94617469575756f), Z2, bc2(-0.31539156525252005f)),
                        mul2(bc2(-1.0925484305920792f), XZ));
                ACC2(4, mul2(bc2(0.5462742152960396f), fma2(Y2, bc2(-1.f), X2)),
                        mul2(bc2(0.5900435899266435f), mul2(Y, fma2(bc2(-3.f), X2, Y2))));
                ACC2(5, mul2(bc2(2.890611442640554f), mul2(XY, Z)),
                        mul2(bc2(0.4570457994644657f), mul2(Y, fma2(bc2(-5.f), Z2, bc2(1.f)))));
                ACC2(6, mul2(bc2(0.3731763325901154f), mul2(Z, fma2(bc2(5.f), Z2, bc2(-3.f)))),
                        mul2(bc2(0.4570457994644657f), mul2(X, fma2(bc2(-5.f), Z2, bc2(1.f)))));
                ACC2(7, mul2(bc2(1.445305721320277f), mul2(Z, fma2(Y2, bc2(-1.f), X2))),
                        mul2(bc2(0.5900435899266435f), mul2(X, fma2(bc2(-3.f), Y2, X2))));
                #undef ACC2
                ca[P] = relu2(a); cb[P] = relu2(b);
            }
            // stage ca/cb into ring (overwrites geo slots; geo no longer needed)
            __syncwarp();
            #pragma unroll
            for (int P = 0; P < NPAIR; ++P) {
                abw[P * 64 + 2 * lane]     = ca[P];
                abw[P * 64 + 2 * lane + 1] = cb[P];
            }
            __syncwarp();
            u64 c10[NPAIR], c11[NPAIR];
            #pragma unroll
            for (int P = 0; P < NPAIR; ++P) { c10[P] = 0ull; c11[P] = 0ull; }
            #pragma unroll 2
            for (int kk = 0; kk < 32; ++kk) {
                float4 w4 = wc1pk[kk * 32 + lane];
                u64 w00 = bc2(w4.x), w01 = bc2(w4.y), w10 = bc2(w4.z), w11 = bc2(w4.w);
                #pragma unroll
                for (int P = 0; P < NPAIR; ++P) {
                    ulonglong2 hab = *(const ulonglong2*)(abw + P * 64 + 2 * kk);
                    c10[P] = fma2(hab.x, w00, fma2(hab.y, w10, c10[P]));
                    c11[P] = fma2(hab.x, w01, fma2(hab.y, w11, c11[P]));
                }
            }
            #pragma unroll
            for (int P = 0; P < NPAIR; ++P) { c10[P] = relu2(c10[P]); c11[P] = relu2(c11[P]); }
            #pragma unroll
            for (int d = 0; d < 3; ++d) {
                u64 wA = bc2(swc2[lane * 3 + d]);
                u64 wB = bc2(swc2[(lane + 32) * 3 + d]);
                #pragma unroll
                for (int P = 0; P < NPAIR; ++P) {
                    u64 s = allsum2(fma2(c10[P], wA, mul2(c11[P], wB)));
                    float r0, r1; upk(s, r0, r1);
                    if (lane == d) {
                        out[(size_t)NPTS * 22 + (size_t)(pbase + P * 2 + 0) * 3 + d] = sigm(r0);
                        out[(size_t)NPTS * 22 + (size_t)(pbase + P * 2 + 1) * 3 + d] = sigm(r1);
                    }
                }
            }
        }
        __syncwarp();
    }
}

extern "C" void kernel_launch(void* const* d_in, const int* in_sizes, int n_in,
                              void* d_out, int out_size) {
    (void)in_sizes; (void)n_in; (void)out_size;
    HGParams prm;
    double pls = exp2(log2(2048.0 * 1.0 / 16.0) / 15.0);
    for (int l = 0; l < 16; ++l) {
        int r = (int)floor(16.0 * pow(pls, (double)l));
        prm.res[l] = r;
        long long r3 = (long long)r * r * r;
        prm.dense[l] = (r3 <= (long long)TSZ) ? 1 : 0;
    }
    size_t smemBytes = (size_t)SMEM_FLOATS * sizeof(float);
    cudaFuncSetAttribute(nerf_kernel, cudaFuncAttributeMaxDynamicSharedMemorySize, (int)smemBytes);
    nerf_kernel<<<NBLOCKS, NTHREADS, smemBytes>>>(
        (const float*)d_in[0], (const float*)d_in[1],
        (const float*)d_in[2], (const float*)d_in[3],
        (const float*)d_in[4], (const float*)d_in[5], (const float*)d_in[6],
        (const float*)d_in[7], (const float*)d_in[8],
        (const float*)d_in[9], (const float*)d_in[10],
        (const float*)d_in[11], (const float*)d_in[12],
        (float*)d_out, prm);
}

// round 16
// speedup vs baseline: 1.1367x; 1.0045x over previous
#include <cuda_runtime.h>
#include <math.h>
#include <stdint.h>

#define NPTS 524288
#define TSZ  524288
#define NTHREADS 256
#define NWARPS_BLK 8
#define NBLOCKS 296
#define FULL 0xffffffffu
#define NPAIR 4   // 8 points per warp iteration

typedef unsigned long long u64;

// ---- shared memory layout (float offsets) ----
#define OFF_WS0PK4  0       // [16][32] float4
#define OFF_WS0TPK4 2048    // [16][32] float4
#define OFF_WS1PK4  4096    // [16][16] float4
#define OFF_WC1PK   5120    // [32][32] float4
#define OFF_WC0SH4  9216    // [8][32] float4
#define OFF_WC0GE4  10240   // [8][32] float4
#define OFF_WN0PK4  11264   // [8][32] float4
#define OFF_WM0PK2  12288   // [8][32] float2
#define OFF_WC2     12800   // [64][3]
#define OFF_WN1     12992   // [64][3]
#define OFF_WM1     13184   // [32]
#define OFF_BM0     13216   // [32]
#define OFF_BM1     13248   // [1]
#define OFF_WS10    13250   // [64] ws1 column 0
#define OFF_DF      13316   // 8 warps * 384 u64 = 6144 floats
#define OFF_ABUF    19460   // 8 warps * 256 u64 = 4096 floats (16B aligned)
#define OFF_XBUF    23556   // 8 warps * 128 floats (2 buffers x 64)
#define SMEM_FLOATS 24580

struct HGParams { int res[16]; int dense[16]; };

__device__ __forceinline__ u64 pk(float lo, float hi) {
    u64 r; asm("mov.b64 %0,{%1,%2};" : "=l"(r) : "f"(lo), "f"(hi)); return r;
}
__device__ __forceinline__ void upk(u64 v, float& lo, float& hi) {
    asm("mov.b64 {%0,%1},%2;" : "=f"(lo), "=f"(hi) : "l"(v));
}
__device__ __forceinline__ u64 bc2(float w) { return pk(w, w); }
__device__ __forceinline__ u64 fma2(u64 a, u64 b, u64 c) {
    u64 d; asm("fma.rn.f32x2 %0,%1,%2,%3;" : "=l"(d) : "l"(a), "l"(b), "l"(c)); return d;
}
__device__ __forceinline__ u64 mul2(u64 a, u64 b) {
    u64 d; asm("mul.rn.f32x2 %0,%1,%2;" : "=l"(d) : "l"(a), "l"(b)); return d;
}
__device__ __forceinline__ u64 add2(u64 a, u64 b) {
    u64 d; asm("add.rn.f32x2 %0,%1,%2;" : "=l"(d) : "l"(a), "l"(b)); return d;
}
__device__ __forceinline__ u64 relu2(u64 v) {
    float a, b; upk(v, a, b); return pk(fmaxf(a, 0.f), fmaxf(b, 0.f));
}
__device__ __forceinline__ u64 allsum2(u64 v) {
    #pragma unroll
    for (int o = 16; o > 0; o >>= 1) v = add2(v, __shfl_xor_sync(FULL, v, o));
    return v;
}
__device__ __forceinline__ float sigm(float v) { return 1.0f / (1.0f + expf(-v)); }
__device__ __forceinline__ float sel3(int lane, float a, float b, float c) {
    return lane == 0 ? a : (lane == 1 ? b : c);
}

extern __shared__ float smem[];

__global__ __launch_bounds__(NTHREADS, 2) void nerf_kernel(
    const float* __restrict__ x,
    const float* __restrict__ tables,
    const float* __restrict__ ws0, const float* __restrict__ ws1,
    const float* __restrict__ wc0, const float* __restrict__ wc1, const float* __restrict__ wc2,
    const float* __restrict__ wn0, const float* __restrict__ wn1,
    const float* __restrict__ wm0, const float* __restrict__ bm0,
    const float* __restrict__ wm1, const float* __restrict__ bm1,
    float* __restrict__ out, HGParams prm)
{
    const int tid = threadIdx.x;
    {
        float4* p0 = (float4*)(smem + OFF_WS0PK4);
        for (int i = tid; i < 512; i += NTHREADS) { int r = i >> 5, c = i & 31;
            p0[i] = make_float4(ws0[(2*r)*64+c], ws0[(2*r)*64+c+32], ws0[(2*r+1)*64+c], ws0[(2*r+1)*64+c+32]); }
        float4* pt4 = (float4*)(smem + OFF_WS0TPK4);
        for (int i = tid; i < 512; i += NTHREADS) { int r = i >> 5, c = i & 31;
            pt4[i] = make_float4(ws0[c*64+2*r], ws0[c*64+2*r+32], ws0[c*64+2*r+1], ws0[c*64+2*r+1+32]); }
        float4* p14 = (float4*)(smem + OFF_WS1PK4);
        for (int i = tid; i < 256; i += NTHREADS) { int r = i >> 4, j = i & 15;
            p14[i] = make_float4(ws1[(2*r)*16+j], ws1[(2*r+32)*16+j], ws1[(2*r+1)*16+j], ws1[(2*r+1+32)*16+j]); }
        float4* pc1 = (float4*)(smem + OFF_WC1PK);
        for (int i = tid; i < 1024; i += NTHREADS) { int kk = i >> 5, c = i & 31;
            pc1[i] = make_float4(wc1[kk*64+c], wc1[kk*64+c+32], wc1[(kk+32)*64+c], wc1[(kk+32)*64+c+32]); }
        float4* psh = (float4*)(smem + OFF_WC0SH4);
        for (int i = tid; i < 256; i += NTHREADS) { int r = i >> 5, c = i & 31;
            psh[i] = make_float4(wc0[(2*r)*64+c], wc0[(2*r)*64+c+32], wc0[(2*r+1)*64+c], wc0[(2*r+1)*64+c+32]); }
        float4* pge = (float4*)(smem + OFF_WC0GE4);
        for (int i = tid; i < 256; i += NTHREADS) { int r = i >> 5, c = i & 31;
            int r0 = 16 + 2*r, r1 = 17 + 2*r;
            float w2 = (r1 <= 30) ? wc0[r1*64+c] : 0.f;
            float w3 = (r1 <= 30) ? wc0[r1*64+c+32] : 0.f;
            pge[i] = make_float4(wc0[r0*64+c], wc0[r0*64+c+32], w2, w3); }
        float4* pn4 = (float4*)(smem + OFF_WN0PK4);
        for (int i = tid; i < 256; i += NTHREADS) { int r = i >> 5, c = i & 31;
            int r1 = 2*r+1;
            float w2 = (r1 <= 14) ? wn0[r1*64+c] : 0.f;
            float w3 = (r1 <= 14) ? wn0[r1*64+c+32] : 0.f;
            pn4[i] = make_float4(wn0[(2*r)*64+c], wn0[(2*r)*64+c+32], w2, w3); }
        float2* pm2 = (float2*)(smem + OFF_WM0PK2);
        for (int i = tid; i < 256; i += NTHREADS) { int r = i >> 5, c = i & 31;
            int r1 = 2*r+1;
            float w1 = (r1 <= 14) ? wm0[r1*32+c] : 0.f;
            pm2[i] = make_float2(wm0[(2*r)*32+c], w1); }
        for (int i = tid; i < 192; i += NTHREADS) smem[OFF_WC2 + i] = wc2[i];
        for (int i = tid; i < 192; i += NTHREADS) smem[OFF_WN1 + i] = wn1[i];
        for (int i = tid; i < 32;  i += NTHREADS) smem[OFF_WM1 + i] = wm1[i];
        for (int i = tid; i < 32;  i += NTHREADS) smem[OFF_BM0 + i] = bm0[i];
        for (int i = tid; i < 64;  i += NTHREADS) smem[OFF_WS10 + i] = ws1[i * 16];
        if (tid == 0) smem[OFF_BM1] = bm1[0];
    }
    __syncthreads();

    const int lane = tid & 31;
    const int warpInBlk = tid >> 5;
    const int gwarp = blockIdx.x * NWARPS_BLK + warpInBlk;
    const int nwarp = gridDim.x * NWARPS_BLK;
    const int j16 = lane & 15;

    const int lvl = lane >> 1;
    const int half = lane & 1;
    const float sxsign = half ? 1.f : -1.f;
    const int res = prm.res[lvl];
    const int dense = prm.dense[lvl];
    const int resm1 = res - 1;
    const float rm1 = (float)resm1;
    const float gscale = rm1 * 0.5f;
    const unsigned my = dense ? (unsigned)res : 2654435761u;
    const unsigned mz = dense ? (unsigned)(res * res) : 805459861u;
    const float2* __restrict__ tabl = ((const float2*)tables) + (size_t)lvl * TSZ;

    const float4* ws0pk4  = (const float4*)(smem + OFF_WS0PK4);
    const float4* ws0tpk4 = (const float4*)(smem + OFF_WS0TPK4);
    const float4* ws1pk4  = (const float4*)(smem + OFF_WS1PK4);
    const float4* wc1pk   = (const float4*)(smem + OFF_WC1PK);
    const float4* wc0sh4  = (const float4*)(smem + OFF_WC0SH4);
    const float4* wc0ge4  = (const float4*)(smem + OFF_WC0GE4);
    const float4* wn0pk4  = (const float4*)(smem + OFF_WN0PK4);
    const float2* wm0pk2  = (const float2*)(smem + OFF_WM0PK2);
    const float* swc2 = smem + OFF_WC2;
    const float* swn1 = smem + OFF_WN1;
    const float* swm1 = smem + OFF_WM1;
    const float* sbm0 = smem + OFF_BM0;
    const float* sws10 = smem + OFF_WS10;
    u64* dfw  = ((u64*)(smem + OFF_DF))  + warpInBlk * (NPAIR * 3 * 32);
    u64* abw  = ((u64*)(smem + OFF_ABUF)) + warpInBlk * 256;   // 64 u64 per P
    float* xbw = smem + OFF_XBUF + warpInBlk * 128;            // 2 buffers x 64 floats

    // ---- prologue: prefetch x for first iteration into buffer 0 ----
    {
        int p0 = gwarp * (2 * NPAIR);
        if (p0 < NPTS) {
            const float* src = x + (size_t)p0 * 6;
            xbw[lane] = __ldg(src + lane);
            if (lane < 16) xbw[32 + lane] = __ldg(src + 32 + lane);
        }
    }
    __syncwarp();

    int it = 0;
    for (int pbase = gwarp * (2 * NPAIR); pbase < NPTS; pbase += nwarp * (2 * NPAIR), ++it) {
        const float* xc = xbw + ((it & 1) * 64);

        // ================= hashgrid gather (x from smem buffer) =================
        u64 encP[NPAIR];
        #pragma unroll
        for (int P = 0; P < NPAIR; ++P) {
            float e2[2], gx2[2], gy2[2], gz2[2];
            #pragma unroll
            for (int q = 0; q < 2; ++q) {
                const float* xp = xc + (2 * P + q) * 6;
                float X = fminf(fmaxf((xp[0] + 1.0f) * 0.5f, 0.0f), 1.0f);
                float Y = fminf(fmaxf((xp[1] + 1.0f) * 0.5f, 0.0f), 1.0f);
                float Z = fminf(fmaxf((xp[2] + 1.0f) * 0.5f, 0.0f), 1.0f);
                float px = X * rm1, py = Y * rm1, pz = Z * rm1;
                float fpx = floorf(px), fpy = floorf(py), fpz = floorf(pz);
                float fx = px - fpx, fy = py - fpy, fz = pz - fpz;
                int ix = (int)fpx, iy = (int)fpy, iz = (int)fpz;
                int ix1 = min(ix + 1, resm1), iy1 = min(iy + 1, resm1), iz1 = min(iz + 1, resm1);
                unsigned tx = half ? (unsigned)ix1 : (unsigned)ix;
                unsigned ay[2] = { (unsigned)iy * my, (unsigned)iy1 * my };
                unsigned az[2] = { (unsigned)iz * mz, (unsigned)iz1 * mz };
                float2 tv[4];
                #pragma unroll
                for (int j = 0; j < 4; ++j) {
                    int by = j >> 1, bz = j & 1;
                    unsigned idx = dense ? (tx + ay[by] + az[bz])
                                         : ((tx ^ ay[by] ^ az[bz]) & (unsigned)(TSZ - 1));
                    tv[j] = __ldg(tabl + idx);
                }
                float oy = 1.f - fy, oz = 1.f - fz;
                float S0 = 0.f, S1 = 0.f, Sy0 = 0.f, Sy1 = 0.f, Sz0 = 0.f, Sz1 = 0.f;
                #pragma unroll
                for (int j = 0; j < 4; ++j) {
                    int by = j >> 1, bz = j & 1;
                    float wy = by ? fy : oy, wz = bz ? fz : oz;
                    float wyz = wy * wz;
                    S0 = fmaf(tv[j].x, wyz, S0);  S1 = fmaf(tv[j].y, wyz, S1);
                    float syw = by ? wz : -wz;
                    Sy0 = fmaf(tv[j].x, syw, Sy0); Sy1 = fmaf(tv[j].y, syw, Sy1);
                    float szw = bz ? wy : -wy;
                    Sz0 = fmaf(tv[j].x, szw, Sz0); Sz1 = fmaf(tv[j].y, szw, Sz1);
                }
                float wxc = half ? fx : 1.f - fx;
                float So  = half ? S1 : S0,  Sp  = half ? S0 : S1;
                float Syo = half ? Sy1 : Sy0, Syp = half ? Sy0 : Sy1;
                float Szo = half ? Sz1 : Sz0, Szp = half ? Sz0 : Sz1;
                u64 A = __shfl_xor_sync(FULL, pk(wxc * Sp, sxsign * Sp), 1);
                u64 B = __shfl_xor_sync(FULL, pk(wxc * Syp, wxc * Szp), 1);
                float er, gxr, gyr, gzr;
                upk(A, er, gxr); upk(B, gyr, gzr);
                e2[q]  = fmaf(wxc, So, er);
                gx2[q] = (fmaf(sxsign, So, gxr)) * gscale;
                gy2[q] = (fmaf(wxc, Syo, gyr)) * gscale;
                gz2[q] = (fmaf(wxc, Szo, gzr)) * gscale;
            }
            encP[P] = pk(e2[0], e2[1]);
            dfw[(P * 3 + 0) * 32 + lane] = pk(gx2[0], gx2[1]);
            dfw[(P * 3 + 1) * 32 + lane] = pk(gy2[0], gy2[1]);
            dfw[(P * 3 + 2) * 32 + lane] = pk(gz2[0], gz2[1]);
        }

        // ---- prefetch x for NEXT iteration into the other buffer (coalesced) ----
        {
            int pnext = pbase + nwarp * (2 * NPAIR);
            if (pnext < NPTS) {
                const float* src = x + (size_t)pnext * 6;
                float* dst = xbw + (((it + 1) & 1) * 64);
                dst[lane] = __ldg(src + lane);
                if (lane < 16) dst[32 + lane] = __ldg(src + 32 + lane);
            }
        }

        // stage enc into activation ring
        __syncwarp();
        #pragma unroll
        for (int P = 0; P < NPAIR; ++P) abw[P * 64 + lane] = encP[P];
        __syncwarp();

        // ================= density layer0 (enc from smem broadcast) =================
        u64 h1[NPAIR][2];
        #pragma unroll
        for (int P = 0; P < NPAIR; ++P) { h1[P][0] = 0ull; h1[P][1] = 0ull; }
        #pragma unroll 4
        for (int i = 0; i < 16; ++i) {
            float4 w4 = ws0pk4[i * 32 + lane];
            u64 wx = bc2(w4.x), wy = bc2(w4.y), wz = bc2(w4.z), ww = bc2(w4.w);
            #pragma unroll
            for (int P = 0; P < NPAIR; ++P) {
                ulonglong2 e01 = *(const ulonglong2*)(abw + P * 64 + 2 * i);
                h1[P][0] = fma2(e01.x, wx, fma2(e01.y, wz, h1[P][0]));
                h1[P][1] = fma2(e01.x, wy, fma2(e01.y, ww, h1[P][1]));
            }
        }
        #pragma unroll
        for (int P = 0; P < NPAIR; ++P) { h1[P][0] = relu2(h1[P][0]); h1[P][1] = relu2(h1[P][1]); }

        // stage h1 into activation ring (overwrites enc)
        __syncwarp();
        #pragma unroll
        for (int P = 0; P < NPAIR; ++P) {
            abw[P * 64 + lane]      = h1[P][0];
            abw[P * 64 + 32 + lane] = h1[P][1];
        }
        __syncwarp();

        // ================= layer1: geo = h1 @ ws1 (pure fma2) =================
        u64 geo[NPAIR];
        #pragma unroll
        for (int P = 0; P < NPAIR; ++P) geo[P] = 0ull;
        #pragma unroll 2
        for (int i = 0; i < 16; ++i) {
            float4 w14 = ws1pk4[i * 16 + j16];
            u64 wA = bc2(w14.x), wB = bc2(w14.y), wC = bc2(w14.z), wD = bc2(w14.w);
            #pragma unroll
            for (int P = 0; P < NPAIR; ++P) {
                ulonglong2 a01 = *(const ulonglong2*)(abw + P * 64 + 2 * i);
                ulonglong2 b01 = *(const ulonglong2*)(abw + P * 64 + 32 + 2 * i);
                geo[P] = fma2(a01.x, wA, fma2(b01.x, wB, fma2(a01.y, wC, fma2(b01.y, wD, geo[P]))));
            }
        }

        // ================= dh per lane (owned k), overwrite ring with dh =================
        {
            float w10a = sws10[lane], w10b = sws10[lane + 32];
            __syncwarp();
            #pragma unroll
            for (int P = 0; P < NPAIR; ++P) {
                float a, b;
                upk(h1[P][0], a, b);
                abw[P * 64 + lane] = pk(a > 0.f ? w10a : 0.f, b > 0.f ? w10a : 0.f);
                upk(h1[P][1], a, b);
                abw[P * 64 + 32 + lane] = pk(a > 0.f ? w10b : 0.f, b > 0.f ? w10b : 0.f);
            }
            __syncwarp();
        }

        // ================= backward: genc = ws0t @ dh (pure fma2) =================
        u64 genc[NPAIR];
        #pragma unroll
        for (int P = 0; P < NPAIR; ++P) genc[P] = 0ull;
        #pragma unroll 2
        for (int i = 0; i < 16; ++i) {
            float4 wst = ws0tpk4[i * 32 + lane];
            u64 sA = bc2(wst.x), sB = bc2(wst.y), sC = bc2(wst.z), sD = bc2(wst.w);
            #pragma unroll
            for (int P = 0; P < NPAIR; ++P) {
                ulonglong2 a01 = *(const ulonglong2*)(abw + P * 64 + 2 * i);
                ulonglong2 b01 = *(const ulonglong2*)(abw + P * 64 + 32 + 2 * i);
                genc[P] = fma2(a01.x, sA, fma2(b01.x, sB, fma2(a01.y, sC, fma2(b01.y, sD, genc[P]))));
            }
        }

        // stage geo into activation ring (overwrites dh)
        __syncwarp();
        #pragma unroll
        for (int P = 0; P < NPAIR; ++P) abw[P * 64 + lane] = geo[P];
        __syncwarp();

        // ================= normal =================
        #pragma unroll
        for (int P = 0; P < NPAIR; ++P) {
            u64 sx = allsum2(mul2(genc[P], dfw[(P * 3 + 0) * 32 + lane]));
            u64 sy = allsum2(mul2(genc[P], dfw[(P * 3 + 1) * 32 + lane]));
            u64 sz = allsum2(mul2(genc[P], dfw[(P * 3 + 2) * 32 + lane]));
            float nx0, nx1, ny0, ny1, nz0, nz1;
            upk(sx, nx0, nx1); upk(sy, ny0, ny1); upk(sz, nz0, nz1);
            #pragma unroll
            for (int q = 0; q < 2; ++q) {
                float n0 = -(q ? nx1 : nx0), n1 = -(q ? ny1 : ny0), n2 = -(q ? nz1 : nz0);
                float inv = 1.0f / fmaxf(sqrtf(n0 * n0 + n1 * n1 + n2 * n2), 1e-8f);
                if (lane < 3)
                    out[(size_t)NPTS * 16 + (size_t)(pbase + P * 2 + q) * 3 + lane] =
                        sel3(lane, n0 * inv, n1 * inv, n2 * inv);
            }
        }

        // ========== merged pred_normal (wn0) + mirror (wm0) broadcast loop ==========
        {
            u64 t0[NPAIR], t1[NPAIR], m[NPAIR];
            #pragma unroll
            for (int P = 0; P < NPAIR; ++P) { t0[P] = 0ull; t1[P] = 0ull; m[P] = bc2(sbm0[lane]); }
            #pragma unroll
            for (int ii = 0; ii < 8; ++ii) {
                float4 w4 = wn0pk4[ii * 32 + lane];
                float2 w2 = wm0pk2[ii * 32 + lane];
                u64 wx = bc2(w4.x), wy = bc2(w4.y), wz = bc2(w4.z), ww = bc2(w4.w);
                u64 mx = bc2(w2.x), mzx = bc2(w2.y);
                #pragma unroll
                for (int P = 0; P < NPAIR; ++P) {
                    u64 g1 = abw[P * 64 + 2 * ii + 1];
                    u64 g2 = abw[P * 64 + 2 * ii + 2];
                    t0[P] = fma2(g1, wx, fma2(g2, wz, t0[P]));
                    t1[P] = fma2(g1, wy, fma2(g2, ww, t1[P]));
                    m[P]  = fma2(g1, mx, fma2(g2, mzx, m[P]));
                }
            }
            // pred_normal reductions + store
            #pragma unroll
            for (int P = 0; P < NPAIR; ++P) { t0[P] = relu2(t0[P]); t1[P] = relu2(t1[P]); }
            #pragma unroll
            for (int P = 0; P < NPAIR; ++P) {
                float pn[3][2];
                #pragma unroll
                for (int d = 0; d < 3; ++d) {
                    u64 wA = bc2(swn1[lane * 3 + d]);
                    u64 wB = bc2(swn1[(lane + 32) * 3 + d]);
                    u64 s = allsum2(fma2(t0[P], wA, mul2(t1[P], wB)));
                    upk(s, pn[d][0], pn[d][1]);
                }
                #pragma unroll
                for (int q = 0; q < 2; ++q) {
                    float n0 = pn[0][q], n1 = pn[1][q], n2 = pn[2][q];
                    float inv = 1.0f / fmaxf(sqrtf(n0 * n0 + n1 * n1 + n2 * n2), 1e-8f);
                    if (lane < 3)
                        out[(size_t)NPTS * 19 + (size_t)(pbase + P * 2 + q) * 3 + lane] =
                            sel3(lane, n0 * inv, n1 * inv, n2 * inv);
                }
            }
            // mirror leaky-relu + reduction + store
            float bm1v = smem[OFF_BM1];
            u64 wv = bc2(swm1[lane]);
            #pragma unroll
            for (int P = 0; P < NPAIR; ++P) {
                float a, b; upk(m[P], a, b);
                a = a > 0.f ? a : 0.01f * a;
                b = b > 0.f ? b : 0.01f * b;
                u64 s = allsum2(mul2(pk(a, b), wv));
                float s0, s1; upk(s, s0, s1);
                if (lane == 0) {
                    out[(size_t)NPTS * 25 + (pbase + P * 2 + 0)] = sigm(s0 + bm1v);
                    out[(size_t)NPTS * 25 + (pbase + P * 2 + 1)] = sigm(s1 + bm1v);
                }
            }
        }

        // ================= sigma + geo_feat =================
        #pragma unroll
        for (int P = 0; P < NPAIR; ++P) {
            float gA, gB; upk(geo[P], gA, gB);
            size_t p0 = (size_t)(pbase + P * 2), p1 = p0 + 1;
            if (lane == 0) { out[p0] = gA; out[p1] = gB; }
            if (lane >= 1 && lane < 16) {
                out[(size_t)NPTS + p0 * 15 + (lane - 1)] = gA;
                out[(size_t)NPTS + p1 * 15 + (lane - 1)] = gB;
            }
        }

        // ================= color =================
        {
            u64 ca[NPAIR], cb[NPAIR];
            #pragma unroll
            for (int P = 0; P < NPAIR; ++P) { ca[P] = 0ull; cb[P] = 0ull; }
            // geo part (geo from smem ring)
            #pragma unroll
            for (int ii = 0; ii < 8; ++ii) {
                float4 w4 = wc0ge4[ii * 32 + lane];
                u64 wx = bc2(w4.x), wy = bc2(w4.y), wz = bc2(w4.z), ww = bc2(w4.w);
                #pragma unroll
                for (int P = 0; P < NPAIR; ++P) {
                    u64 g1 = abw[P * 64 + 2 * ii + 1];
                    u64 g2 = abw[P * 64 + 2 * ii + 2];
                    ca[P] = fma2(g1, wx, fma2(g2, wz, ca[P]));
                    cb[P] = fma2(g1, wy, fma2(g2, ww, cb[P]));
                }
            }
            // SH part, dir straight from the x buffer
            #pragma unroll
            for (int P = 0; P < NPAIR; ++P) {
                const float* x0 = xc + (2 * P) * 6;
                const float* x1 = xc + (2 * P + 1) * 6;
                u64 X = pk(x0[3], x1[3]);
                u64 Y = pk(x0[4], x1[4]);
                u64 Z = pk(x0[5], x1[5]);
                u64 XY = mul2(X, Y), XZ = mul2(X, Z), YZ = mul2(Y, Z);
                u64 X2 = mul2(X, X), Y2 = mul2(Y, Y), Z2 = mul2(Z, Z);
                u64 a = ca[P], b = cb[P];
                #define ACC2(ii, e0, e1) { u64 s0_ = (e0), s1_ = (e1); float4 w_ = wc0sh4[(ii) * 32 + lane]; \
                    a = fma2(s0_, bc2(w_.x), fma2(s1_, bc2(w_.z), a)); \
                    b = fma2(s0_, bc2(w_.y), fma2(s1_, bc2(w_.w), b)); }
                ACC2(0, bc2(0.28209479177387814f),
                        mul2(bc2(-0.48860251190291987f), Y));
                ACC2(1, mul2(bc2(0.48860251190291987f), Z),
                        mul2(bc2(-0.48860251190291987f), X));
                ACC2(2, mul2(bc2(1.0925484305920792f), XY),
                        mul2(bc2(-1.0925484305920792f), YZ));
                ACC2(3, fma2(bc2(0.94617469575756f), Z2, bc2(-0.31539156525252005f)),
                        mul2(bc2(-1.0925484305920792f), XZ));
                ACC2(4, mul2(bc2(0.5462742152960396f), fma2(Y2, bc2(-1.f), X2)),
                        mul2(bc2(0.5900435899266435f), mul2(Y, fma2(bc2(-3.f), X2, Y2))));
                ACC2(5, mul2(bc2(2.890611442640554f), mul2(XY, Z)),
                        mul2(bc2(0.4570457994644657f), mul2(Y, fma2(bc2(-5.f), Z2, bc2(1.f)))));
                ACC2(6, mul2(bc2(0.3731763325901154f), mul2(Z, fma2(bc2(5.f), Z2, bc2(-3.f)))),
                        mul2(bc2(0.4570457994644657f), mul2(X, fma2(bc2(-5.f), Z2, bc2(1.f)))));
                ACC2(7, mul2(bc2(1.445305721320277f), mul2(Z, fma2(Y2, bc2(-1.f), X2))),
                        mul2(bc2(0.5900435899266435f), mul2(X, fma2(bc2(-3.f), Y2, X2))));
                #undef ACC2
                ca[P] = relu2(a); cb[P] = relu2(b);
            }
            // stage ca/cb into ring (overwrites geo slots; geo no longer needed)
            __syncwarp();
            #pragma unroll
            for (int P = 0; P < NPAIR; ++P) {
                abw[P * 64 + 2 * lane]     = ca[P];
                abw[P * 64 + 2 * lane + 1] = cb[P];
            }
            __syncwarp();
            u64 c10[NPAIR], c11[NPAIR];
            #pragma unroll
            for (int P = 0; P < NPAIR; ++P) { c10[P] = 0ull; c11[P] = 0ull; }
            #pragma unroll 2
            for (int kk = 0; kk < 32; ++kk) {
                float4 w4 = wc1pk[kk * 32 + lane];
                u64 w00 = bc2(w4.x), w01 = bc2(w4.y), w10 = bc2(w4.z), w11 = bc2(w4.w);
                #pragma unroll
                for (int P = 0; P < NPAIR; ++P) {
                    ulonglong2 hab = *(const ulonglong2*)(abw + P * 64 + 2 * kk);
                    c10[P] = fma2(hab.x, w00, fma2(hab.y, w10, c10[P]));
                    c11[P] = fma2(hab.x, w01, fma2(hab.y, w11, c11[P]));
                }
            }
            #pragma unroll
            for (int P = 0; P < NPAIR; ++P) { c10[P] = relu2(c10[P]); c11[P] = relu2(c11[P]); }
            #pragma unroll
            for (int d = 0; d < 3; ++d) {
                u64 wA = bc2(swc2[lane * 3 + d]);
                u64 wB = bc2(swc2[(lane + 32) * 3 + d]);
                #pragma unroll
                for (int P = 0; P < NPAIR; ++P) {
                    u64 s = allsum2(fma2(c10[P], wA, mul2(c11[P], wB)));
                    float r0, r1; upk(s, r0, r1);
                    if (lane == d) {
                        out[(size_t)NPTS * 22 + (size_t)(pbase + P * 2 + 0) * 3 + d] = sigm(r0);
                        out[(size_t)NPTS * 22 + (size_t)(pbase + P * 2 + 1) * 3 + d] = sigm(r1);
                    }
                }
            }
        }
        __syncwarp();
    }
}

extern "C" void kernel_launch(void* const* d_in, const int* in_sizes, int n_in,
                              void* d_out, int out_size) {
    (void)in_sizes; (void)n_in; (void)out_size;
    HGParams prm;
    double pls = exp2(log2(2048.0 * 1.0 / 16.0) / 15.0);
    for (int l = 0; l < 16; ++l) {
        int r = (int)floor(16.0 * pow(pls, (double)l));
        prm.res[l] = r;
        long long r3 = (long long)r * r * r;
        prm.dense[l] = (r3 <= (long long)TSZ) ? 1 : 0;
    }
    size_t smemBytes = (size_t)SMEM_FLOATS * sizeof(float);
    cudaFuncSetAttribute(nerf_kernel, cudaFuncAttributeMaxDynamicSharedMemorySize, (int)smemBytes);
    nerf_kernel<<<NBLOCKS, NTHREADS, smemBytes>>>(
        (const float*)d_in[0], (const float*)d_in[1],
        (const float*)d_in[2], (const float*)d_in[3],
        (const float*)d_in[4], (const float*)d_in[5], (const float*)d_in[6],
        (const float*)d_in[7], (const float*)d_in[8],
        (const float*)d_in[9], (const float*)d_in[10],
        (const float*)d_in[11], (const float*)d_in[12],
        (float*)d_out, prm);
}

// round 17
// speedup vs baseline: 1.2143x; 1.0682x over previous
#include <cuda_runtime.h>
#include <math.h>
#include <stdint.h>

#define NPTS 524288
#define TSZ  524288
#define NTHREADS 256
#define NWARPS_BLK 8
#define NBLOCKS 296
#define FULL 0xffffffffu
#define NPAIR 4   // 8 points per warp iteration

typedef unsigned long long u64;

// ---- shared memory layout (float offsets) ----
#define OFF_WS0PK4  0       // [16][32] float4
#define OFF_WS0TPK4 2048    // [16][32] float4
#define OFF_WS1PK4  4096    // [16][16] float4
#define OFF_WC1PK   5120    // [32][32] float4
#define OFF_WC0SH4  9216    // [8][32] float4
#define OFF_WC0GE4  10240   // [8][32] float4
#define OFF_WN0PK4  11264   // [8][32] float4
#define OFF_WM0PK2  12288   // [8][32] float2
#define OFF_WC2     12800   // [64][3]
#define OFF_WN1     12992   // [64][3]
#define OFF_WM1     13184   // [32]
#define OFF_BM0     13216   // [32]
#define OFF_BM1     13248   // [1]
#define OFF_WS10    13250   // [64] ws1 column 0
#define OFF_DF      13316   // 8 warps * 384 u64 = 6144 floats
#define OFF_ABUF    19460   // 8 warps * 256 u64 = 4096 floats (16B aligned)
#define OFF_XBUF    23556   // 8 warps * 128 floats (2 buffers x 64)
#define SMEM_FLOATS 24580

struct HGParams { int res[16]; int dense[16]; };

__device__ __forceinline__ u64 pk(float lo, float hi) {
    u64 r; asm("mov.b64 %0,{%1,%2};" : "=l"(r) : "f"(lo), "f"(hi)); return r;
}
__device__ __forceinline__ void upk(u64 v, float& lo, float& hi) {
    asm("mov.b64 {%0,%1},%2;" : "=f"(lo), "=f"(hi) : "l"(v));
}
__device__ __forceinline__ u64 bc2(float w) { return pk(w, w); }
__device__ __forceinline__ u64 fma2(u64 a, u64 b, u64 c) {
    u64 d; asm("fma.rn.f32x2 %0,%1,%2,%3;" : "=l"(d) : "l"(a), "l"(b), "l"(c)); return d;
}
__device__ __forceinline__ u64 mul2(u64 a, u64 b) {
    u64 d; asm("mul.rn.f32x2 %0,%1,%2;" : "=l"(d) : "l"(a), "l"(b)); return d;
}
__device__ __forceinline__ u64 add2(u64 a, u64 b) {
    u64 d; asm("add.rn.f32x2 %0,%1,%2;" : "=l"(d) : "l"(a), "l"(b)); return d;
}
__device__ __forceinline__ u64 relu2(u64 v) {
    float a, b; upk(v, a, b); return pk(fmaxf(a, 0.f), fmaxf(b, 0.f));
}
__device__ __forceinline__ u64 allsum2(u64 v) {
    #pragma unroll
    for (int o = 16; o > 0; o >>= 1) v = add2(v, __shfl_xor_sync(FULL, v, o));
    return v;
}
__device__ __forceinline__ float sigm(float v) {
    return __fdividef(1.0f, 1.0f + __expf(-v));
}
__device__ __forceinline__ float invn(float nn) {
    return __fdividef(1.0f, fmaxf(nn, 1e-8f));
}
__device__ __forceinline__ float sel3(int lane, float a, float b, float c) {
    return lane == 0 ? a : (lane == 1 ? b : c);
}

extern __shared__ float smem[];

__global__ __launch_bounds__(NTHREADS, 2) void nerf_kernel(
    const float* __restrict__ x,
    const float* __restrict__ tables,
    const float* __restrict__ ws0, const float* __restrict__ ws1,
    const float* __restrict__ wc0, const float* __restrict__ wc1, const float* __restrict__ wc2,
    const float* __restrict__ wn0, const float* __restrict__ wn1,
    const float* __restrict__ wm0, const float* __restrict__ bm0,
    const float* __restrict__ wm1, const float* __restrict__ bm1,
    float* __restrict__ out, HGParams prm)
{
    const int tid = threadIdx.x;
    {
        float4* p0 = (float4*)(smem + OFF_WS0PK4);
        for (int i = tid; i < 512; i += NTHREADS) { int r = i >> 5, c = i & 31;
            p0[i] = make_float4(ws0[(2*r)*64+c], ws0[(2*r)*64+c+32], ws0[(2*r+1)*64+c], ws0[(2*r+1)*64+c+32]); }
        float4* pt4 = (float4*)(smem + OFF_WS0TPK4);
        for (int i = tid; i < 512; i += NTHREADS) { int r = i >> 5, c = i & 31;
            pt4[i] = make_float4(ws0[c*64+2*r], ws0[c*64+2*r+32], ws0[c*64+2*r+1], ws0[c*64+2*r+1+32]); }
        float4* p14 = (float4*)(smem + OFF_WS1PK4);
        for (int i = tid; i < 256; i += NTHREADS) { int r = i >> 4, j = i & 15;
            p14[i] = make_float4(ws1[(2*r)*16+j], ws1[(2*r+32)*16+j], ws1[(2*r+1)*16+j], ws1[(2*r+1+32)*16+j]); }
        float4* pc1 = (float4*)(smem + OFF_WC1PK);
        for (int i = tid; i < 1024; i += NTHREADS) { int kk = i >> 5, c = i & 31;
            pc1[i] = make_float4(wc1[kk*64+c], wc1[kk*64+c+32], wc1[(kk+32)*64+c], wc1[(kk+32)*64+c+32]); }
        float4* psh = (float4*)(smem + OFF_WC0SH4);
        for (int i = tid; i < 256; i += NTHREADS) { int r = i >> 5, c = i & 31;
            psh[i] = make_float4(wc0[(2*r)*64+c], wc0[(2*r)*64+c+32], wc0[(2*r+1)*64+c], wc0[(2*r+1)*64+c+32]); }
        float4* pge = (float4*)(smem + OFF_WC0GE4);
        for (int i = tid; i < 256; i += NTHREADS) { int r = i >> 5, c = i & 31;
            int r0 = 16 + 2*r, r1 = 17 + 2*r;
            float w2 = (r1 <= 30) ? wc0[r1*64+c] : 0.f;
            float w3 = (r1 <= 30) ? wc0[r1*64+c+32] : 0.f;
            pge[i] = make_float4(wc0[r0*64+c], wc0[r0*64+c+32], w2, w3); }
        float4* pn4 = (float4*)(smem + OFF_WN0PK4);
        for (int i = tid; i < 256; i += NTHREADS) { int r = i >> 5, c = i & 31;
            int r1 = 2*r+1;
            float w2 = (r1 <= 14) ? wn0[r1*64+c] : 0.f;
            float w3 = (r1 <= 14) ? wn0[r1*64+c+32] : 0.f;
            pn4[i] = make_float4(wn0[(2*r)*64+c], wn0[(2*r)*64+c+32], w2, w3); }
        float2* pm2 = (float2*)(smem + OFF_WM0PK2);
        for (int i = tid; i < 256; i += NTHREADS) { int r = i >> 5, c = i & 31;
            int r1 = 2*r+1;
            float w1 = (r1 <= 14) ? wm0[r1*32+c] : 0.f;
            pm2[i] = make_float2(wm0[(2*r)*32+c], w1); }
        for (int i = tid; i < 192; i += NTHREADS) smem[OFF_WC2 + i] = wc2[i];
        for (int i = tid; i < 192; i += NTHREADS) smem[OFF_WN1 + i] = wn1[i];
        for (int i = tid; i < 32;  i += NTHREADS) smem[OFF_WM1 + i] = wm1[i];
        for (int i = tid; i < 32;  i += NTHREADS) smem[OFF_BM0 + i] = bm0[i];
        for (int i = tid; i < 64;  i += NTHREADS) smem[OFF_WS10 + i] = ws1[i * 16];
        if (tid == 0) smem[OFF_BM1] = bm1[0];
    }
    __syncthreads();

    const int lane = tid & 31;
    const int warpInBlk = tid >> 5;
    const int gwarp = blockIdx.x * NWARPS_BLK + warpInBlk;
    const int nwarp = gridDim.x * NWARPS_BLK;
    const int j16 = lane & 15;

    const int lvl = lane >> 1;
    const int half = lane & 1;
    const float sxsign = half ? 1.f : -1.f;
    const int res = prm.res[lvl];
    const int dense = prm.dense[lvl];
    const int resm1 = res - 1;
    const float rm1 = (float)resm1;
    const float gscale = rm1 * 0.5f;
    const unsigned my = dense ? (unsigned)res : 2654435761u;
    const unsigned mz = dense ? (unsigned)(res * res) : 805459861u;
    const float2* __restrict__ tabl = ((const float2*)tables) + (size_t)lvl * TSZ;

    const float4* ws0pk4  = (const float4*)(smem + OFF_WS0PK4);
    const float4* ws0tpk4 = (const float4*)(smem + OFF_WS0TPK4);
    const float4* ws1pk4  = (const float4*)(smem + OFF_WS1PK4);
    const float4* wc1pk   = (const float4*)(smem + OFF_WC1PK);
    const float4* wc0sh4  = (const float4*)(smem + OFF_WC0SH4);
    const float4* wc0ge4  = (const float4*)(smem + OFF_WC0GE4);
    const float4* wn0pk4  = (const float4*)(smem + OFF_WN0PK4);
    const float2* wm0pk2  = (const float2*)(smem + OFF_WM0PK2);
    const float* swc2 = smem + OFF_WC2;
    const float* swn1 = smem + OFF_WN1;
    const float* swm1 = smem + OFF_WM1;
    const float* sbm0 = smem + OFF_BM0;
    const float* sws10 = smem + OFF_WS10;
    u64* dfw  = ((u64*)(smem + OFF_DF))  + warpInBlk * (NPAIR * 3 * 32);
    u64* abw  = ((u64*)(smem + OFF_ABUF)) + warpInBlk * 256;   // 64 u64 per P
    float* xbw = smem + OFF_XBUF + warpInBlk * 128;            // 2 buffers x 64 floats

    // ---- prologue: prefetch x for first iteration into buffer 0 ----
    {
        int p0 = gwarp * (2 * NPAIR);
        if (p0 < NPTS) {
            const float* src = x + (size_t)p0 * 6;
            xbw[lane] = __ldg(src + lane);
            if (lane < 16) xbw[32 + lane] = __ldg(src + 32 + lane);
        }
    }
    __syncwarp();

    int it = 0;
    for (int pbase = gwarp * (2 * NPAIR); pbase < NPTS; pbase += nwarp * (2 * NPAIR), ++it) {
        const float* xc = xbw + ((it & 1) * 64);

        // ================= hashgrid gather (x from smem buffer) =================
        u64 encP[NPAIR];
        #pragma unroll
        for (int P = 0; P < NPAIR; ++P) {
            float e2[2], gx2[2], gy2[2], gz2[2];
            #pragma unroll
            for (int q = 0; q < 2; ++q) {
                const float* xp = xc + (2 * P + q) * 6;
                float X = fminf(fmaxf((xp[0] + 1.0f) * 0.5f, 0.0f), 1.0f);
                float Y = fminf(fmaxf((xp[1] + 1.0f) * 0.5f, 0.0f), 1.0f);
                float Z = fminf(fmaxf((xp[2] + 1.0f) * 0.5f, 0.0f), 1.0f);
                float px = X * rm1, py = Y * rm1, pz = Z * rm1;
                float fpx = floorf(px), fpy = floorf(py), fpz = floorf(pz);
                float fx = px - fpx, fy = py - fpy, fz = pz - fpz;
                int ix = (int)fpx, iy = (int)fpy, iz = (int)fpz;
                int ix1 = min(ix + 1, resm1), iy1 = min(iy + 1, resm1), iz1 = min(iz + 1, resm1);
                unsigned tx = half ? (unsigned)ix1 : (unsigned)ix;
                unsigned ay[2] = { (unsigned)iy * my, (unsigned)iy1 * my };
                unsigned az[2] = { (unsigned)iz * mz, (unsigned)iz1 * mz };
                float2 tv[4];
                #pragma unroll
                for (int j = 0; j < 4; ++j) {
                    int by = j >> 1, bz = j & 1;
                    unsigned idx = dense ? (tx + ay[by] + az[bz])
                                         : ((tx ^ ay[by] ^ az[bz]) & (unsigned)(TSZ - 1));
                    tv[j] = __ldg(tabl + idx);
                }
                float oy = 1.f - fy, oz = 1.f - fz;
                float S0 = 0.f, S1 = 0.f, Sy0 = 0.f, Sy1 = 0.f, Sz0 = 0.f, Sz1 = 0.f;
                #pragma unroll
                for (int j = 0; j < 4; ++j) {
                    int by = j >> 1, bz = j & 1;
                    float wy = by ? fy : oy, wz = bz ? fz : oz;
                    float wyz = wy * wz;
                    S0 = fmaf(tv[j].x, wyz, S0);  S1 = fmaf(tv[j].y, wyz, S1);
                    float syw = by ? wz : -wz;
                    Sy0 = fmaf(tv[j].x, syw, Sy0); Sy1 = fmaf(tv[j].y, syw, Sy1);
                    float szw = bz ? wy : -wy;
                    Sz0 = fmaf(tv[j].x, szw, Sz0); Sz1 = fmaf(tv[j].y, szw, Sz1);
                }
                float wxc = half ? fx : 1.f - fx;
                float So  = half ? S1 : S0,  Sp  = half ? S0 : S1;
                float Syo = half ? Sy1 : Sy0, Syp = half ? Sy0 : Sy1;
                float Szo = half ? Sz1 : Sz0, Szp = half ? Sz0 : Sz1;
                u64 A = __shfl_xor_sync(FULL, pk(wxc * Sp, sxsign * Sp), 1);
                u64 B = __shfl_xor_sync(FULL, pk(wxc * Syp, wxc * Szp), 1);
                float er, gxr, gyr, gzr;
                upk(A, er, gxr); upk(B, gyr, gzr);
                e2[q]  = fmaf(wxc, So, er);
                gx2[q] = (fmaf(sxsign, So, gxr)) * gscale;
                gy2[q] = (fmaf(wxc, Syo, gyr)) * gscale;
                gz2[q] = (fmaf(wxc, Szo, gzr)) * gscale;
            }
            encP[P] = pk(e2[0], e2[1]);
            dfw[(P * 3 + 0) * 32 + lane] = pk(gx2[0], gx2[1]);
            dfw[(P * 3 + 1) * 32 + lane] = pk(gy2[0], gy2[1]);
            dfw[(P * 3 + 2) * 32 + lane] = pk(gz2[0], gz2[1]);
        }

        // ---- prefetch x for NEXT iteration into the other buffer (coalesced) ----
        {
            int pnext = pbase + nwarp * (2 * NPAIR);
            if (pnext < NPTS) {
                const float* src = x + (size_t)pnext * 6;
                float* dst = xbw + (((it + 1) & 1) * 64);
                dst[lane] = __ldg(src + lane);
                if (lane < 16) dst[32 + lane] = __ldg(src + 32 + lane);
            }
        }

        // stage enc into activation ring
        __syncwarp();
        #pragma unroll
        for (int P = 0; P < NPAIR; ++P) abw[P * 64 + lane] = encP[P];
        __syncwarp();

        // ================= density layer0 (enc from smem broadcast) =================
        u64 h1[NPAIR][2];
        #pragma unroll
        for (int P = 0; P < NPAIR; ++P) { h1[P][0] = 0ull; h1[P][1] = 0ull; }
        #pragma unroll 4
        for (int i = 0; i < 16; ++i) {
            float4 w4 = ws0pk4[i * 32 + lane];
            u64 wx = bc2(w4.x), wy = bc2(w4.y), wz = bc2(w4.z), ww = bc2(w4.w);
            #pragma unroll
            for (int P = 0; P < NPAIR; ++P) {
                ulonglong2 e01 = *(const ulonglong2*)(abw + P * 64 + 2 * i);
                h1[P][0] = fma2(e01.x, wx, fma2(e01.y, wz, h1[P][0]));
                h1[P][1] = fma2(e01.x, wy, fma2(e01.y, ww, h1[P][1]));
            }
        }
        #pragma unroll
        for (int P = 0; P < NPAIR; ++P) { h1[P][0] = relu2(h1[P][0]); h1[P][1] = relu2(h1[P][1]); }

        // stage h1 into activation ring (overwrites enc)
        __syncwarp();
        #pragma unroll
        for (int P = 0; P < NPAIR; ++P) {
            abw[P * 64 + lane]      = h1[P][0];
            abw[P * 64 + 32 + lane] = h1[P][1];
        }
        __syncwarp();

        // ================= layer1: geo = h1 @ ws1 (pure fma2) =================
        u64 geo[NPAIR];
        #pragma unroll
        for (int P = 0; P < NPAIR; ++P) geo[P] = 0ull;
        #pragma unroll 2
        for (int i = 0; i < 16; ++i) {
            float4 w14 = ws1pk4[i * 16 + j16];
            u64 wA = bc2(w14.x), wB = bc2(w14.y), wC = bc2(w14.z), wD = bc2(w14.w);
            #pragma unroll
            for (int P = 0; P < NPAIR; ++P) {
                ulonglong2 a01 = *(const ulonglong2*)(abw + P * 64 + 2 * i);
                ulonglong2 b01 = *(const ulonglong2*)(abw + P * 64 + 32 + 2 * i);
                geo[P] = fma2(a01.x, wA, fma2(b01.x, wB, fma2(a01.y, wC, fma2(b01.y, wD, geo[P]))));
            }
        }

        // ================= dh per lane (owned k), overwrite ring with dh =================
        {
            float w10a = sws10[lane], w10b = sws10[lane + 32];
            __syncwarp();
            #pragma unroll
            for (int P = 0; P < NPAIR; ++P) {
                float a, b;
                upk(h1[P][0], a, b);
                abw[P * 64 + lane] = pk(a > 0.f ? w10a : 0.f, b > 0.f ? w10a : 0.f);
                upk(h1[P][1], a, b);
                abw[P * 64 + 32 + lane] = pk(a > 0.f ? w10b : 0.f, b > 0.f ? w10b : 0.f);
            }
            __syncwarp();
        }

        // ================= backward: genc = ws0t @ dh (pure fma2) =================
        u64 genc[NPAIR];
        #pragma unroll
        for (int P = 0; P < NPAIR; ++P) genc[P] = 0ull;
        #pragma unroll 2
        for (int i = 0; i < 16; ++i) {
            float4 wst = ws0tpk4[i * 32 + lane];
            u64 sA = bc2(wst.x), sB = bc2(wst.y), sC = bc2(wst.z), sD = bc2(wst.w);
            #pragma unroll
            for (int P = 0; P < NPAIR; ++P) {
                ulonglong2 a01 = *(const ulonglong2*)(abw + P * 64 + 2 * i);
                ulonglong2 b01 = *(const ulonglong2*)(abw + P * 64 + 32 + 2 * i);
                genc[P] = fma2(a01.x, sA, fma2(b01.x, sB, fma2(a01.y, sC, fma2(b01.y, sD, genc[P]))));
            }
        }

        // stage geo into activation ring (overwrites dh)
        __syncwarp();
        #pragma unroll
        for (int P = 0; P < NPAIR; ++P) abw[P * 64 + lane] = geo[P];
        __syncwarp();

        // ================= normal =================
        #pragma unroll
        for (int P = 0; P < NPAIR; ++P) {
            u64 sx = allsum2(mul2(genc[P], dfw[(P * 3 + 0) * 32 + lane]));
            u64 sy = allsum2(mul2(genc[P], dfw[(P * 3 + 1) * 32 + lane]));
            u64 sz = allsum2(mul2(genc[P], dfw[(P * 3 + 2) * 32 + lane]));
            float nx0, nx1, ny0, ny1, nz0, nz1;
            upk(sx, nx0, nx1); upk(sy, ny0, ny1); upk(sz, nz0, nz1);
            #pragma unroll
            for (int q = 0; q < 2; ++q) {
                float n0 = -(q ? nx1 : nx0), n1 = -(q ? ny1 : ny0), n2 = -(q ? nz1 : nz0);
                float inv = invn(sqrtf(n0 * n0 + n1 * n1 + n2 * n2));
                if (lane < 3)
                    out[(size_t)NPTS * 16 + (size_t)(pbase + P * 2 + q) * 3 + lane] =
                        sel3(lane, n0 * inv, n1 * inv, n2 * inv);
            }
        }

        // ========== merged pred_normal (wn0) + mirror (wm0) broadcast loop ==========
        {
            u64 t0[NPAIR], t1[NPAIR], m[NPAIR];
            #pragma unroll
            for (int P = 0; P < NPAIR; ++P) { t0[P] = 0ull; t1[P] = 0ull; m[P] = bc2(sbm0[lane]); }
            #pragma unroll
            for (int ii = 0; ii < 8; ++ii) {
                float4 w4 = wn0pk4[ii * 32 + lane];
                float2 w2 = wm0pk2[ii * 32 + lane];
                u64 wx = bc2(w4.x), wy = bc2(w4.y), wz = bc2(w4.z), ww = bc2(w4.w);
                u64 mx = bc2(w2.x), mzx = bc2(w2.y);
                #pragma unroll
                for (int P = 0; P < NPAIR; ++P) {
                    u64 g1 = abw[P * 64 + 2 * ii + 1];
                    u64 g2 = abw[P * 64 + 2 * ii + 2];
                    t0[P] = fma2(g1, wx, fma2(g2, wz, t0[P]));
                    t1[P] = fma2(g1, wy, fma2(g2, ww, t1[P]));
                    m[P]  = fma2(g1, mx, fma2(g2, mzx, m[P]));
                }
            }
            // pred_normal reductions + store
            #pragma unroll
            for (int P = 0; P < NPAIR; ++P) { t0[P] = relu2(t0[P]); t1[P] = relu2(t1[P]); }
            #pragma unroll
            for (int P = 0; P < NPAIR; ++P) {
                float pn[3][2];
                #pragma unroll
                for (int d = 0; d < 3; ++d) {
                    u64 wA = bc2(swn1[lane * 3 + d]);
                    u64 wB = bc2(swn1[(lane + 32) * 3 + d]);
                    u64 s = allsum2(fma2(t0[P], wA, mul2(t1[P], wB)));
                    upk(s, pn[d][0], pn[d][1]);
                }
                #pragma unroll
                for (int q = 0; q < 2; ++q) {
                    float n0 = pn[0][q], n1 = pn[1][q], n2 = pn[2][q];
                    float inv = invn(sqrtf(n0 * n0 + n1 * n1 + n2 * n2));
                    if (lane < 3)
                        out[(size_t)NPTS * 19 + (size_t)(pbase + P * 2 + q) * 3 + lane] =
                            sel3(lane, n0 * inv, n1 * inv, n2 * inv);
                }
            }
            // mirror leaky-relu + reduction + store
            float bm1v = smem[OFF_BM1];
            u64 wv = bc2(swm1[lane]);
            #pragma unroll
            for (int P = 0; P < NPAIR; ++P) {
                float a, b; upk(m[P], a, b);
                a = a > 0.f ? a : 0.01f * a;
                b = b > 0.f ? b : 0.01f * b;
                u64 s = allsum2(mul2(pk(a, b), wv));
                float s0, s1; upk(s, s0, s1);
                if (lane == 0) {
                    out[(size_t)NPTS * 25 + (pbase + P * 2 + 0)] = sigm(s0 + bm1v);
                    out[(size_t)NPTS * 25 + (pbase + P * 2 + 1)] = sigm(s1 + bm1v);
                }
            }
        }

        // ================= sigma + geo_feat =================
        #pragma unroll
        for (int P = 0; P < NPAIR; ++P) {
            float gA, gB; upk(geo[P], gA, gB);
            size_t p0 = (size_t)(pbase + P * 2), p1 = p0 + 1;
            if (lane == 0) { out[p0] = gA; out[p1] = gB; }
            if (lane >= 1 && lane < 16) {
                out[(size_t)NPTS + p0 * 15 + (lane - 1)] = gA;
                out[(size_t)NPTS + p1 * 15 + (lane - 1)] = gB;
            }
        }

        // ================= color =================
        {
            u64 ca[NPAIR], cb[NPAIR];
            #pragma unroll
            for (int P = 0; P < NPAIR; ++P) { ca[P] = 0ull; cb[P] = 0ull; }
            // geo part (geo from smem ring)
            #pragma unroll
            for (int ii = 0; ii < 8; ++ii) {
                float4 w4 = wc0ge4[ii * 32 + lane];
                u64 wx = bc2(w4.x), wy = bc2(w4.y), wz = bc2(w4.z), ww = bc2(w4.w);
                #pragma unroll
                for (int P = 0; P < NPAIR; ++P) {
                    u64 g1 = abw[P * 64 + 2 * ii + 1];
                    u64 g2 = abw[P * 64 + 2 * ii + 2];
                    ca[P] = fma2(g1, wx, fma2(g2, wz, ca[P]));
                    cb[P] = fma2(g1, wy, fma2(g2, ww, cb[P]));
                }
            }
            // SH part, dir straight from the x buffer
            #pragma unroll
            for (int P = 0; P < NPAIR; ++P) {
                const float* x0 = xc + (2 * P) * 6;
                const float* x1 = xc + (2 * P + 1) * 6;
                u64 X = pk(x0[3], x1[3]);
                u64 Y = pk(x0[4], x1[4]);
                u64 Z = pk(x0[5], x1[5]);
                u64 XY = mul2(X, Y), XZ = mul2(X, Z), YZ = mul2(Y, Z);
                u64 X2 = mul2(X, X), Y2 = mul2(Y, Y), Z2 = mul2(Z, Z);
                u64 a = ca[P], b = cb[P];
                #define ACC2(ii, e0, e1) { u64 s0_ = (e0), s1_ = (e1); float4 w_ = wc0sh4[(ii) * 32 + lane]; \
                    a = fma2(s0_, bc2(w_.x), fma2(s1_, bc2(w_.z), a)); \
                    b = fma2(s0_, bc2(w_.y), fma2(s1_, bc2(w_.w), b)); }
                ACC2(0, bc2(0.28209479177387814f),
                        mul2(bc2(-0.48860251190291987f), Y));
                ACC2(1, mul2(bc2(0.48860251190291987f), Z),
                        mul2(bc2(-0.48860251190291987f), X));
                ACC2(2, mul2(bc2(1.0925484305920792f), XY),
                        mul2(bc2(-1.0925484305920792f), YZ));
                ACC2(3, fma2(bc2(0.94617469575756f), Z2, bc2(-0.31539156525252005f)),
                        mul2(bc2(-1.0925484305920792f), XZ));
                ACC2(4, mul2(bc2(0.5462742152960396f), fma2(Y2, bc2(-1.f), X2)),
                        mul2(bc2(0.5900435899266435f), mul2(Y, fma2(bc2(-3.f), X2, Y2))));
                ACC2(5, mul2(bc2(2.890611442640554f), mul2(XY, Z)),
                        mul2(bc2(0.4570457994644657f), mul2(Y, fma2(bc2(-5.f), Z2, bc2(1.f)))));
                ACC2(6, mul2(bc2(0.3731763325901154f), mul2(Z, fma2(bc2(5.f), Z2, bc2(-3.f)))),
                        mul2(bc2(0.4570457994644657f), mul2(X, fma2(bc2(-5.f), Z2, bc2(1.f)))));
                ACC2(7, mul2(bc2(1.445305721320277f), mul2(Z, fma2(Y2, bc2(-1.f), X2))),
                        mul2(bc2(0.5900435899266435f), mul2(X, fma2(bc2(-3.f), Y2, X2))));
                #undef ACC2
                ca[P] = relu2(a); cb[P] = relu2(b);
            }
            // stage ca/cb into ring (overwrites geo slots; geo no longer needed)
            __syncwarp();
            #pragma unroll
            for (int P = 0; P < NPAIR; ++P) {
                abw[P * 64 + 2 * lane]     = ca[P];
                abw[P * 64 + 2 * lane + 1] = cb[P];
            }
            __syncwarp();
            u64 c10[NPAIR], c11[NPAIR];
            #pragma unroll
            for (int P = 0; P < NPAIR; ++P) { c10[P] = 0ull; c11[P] = 0ull; }
            #pragma unroll 2
            for (int kk = 0; kk < 32; ++kk) {
                float4 w4 = wc1pk[kk * 32 + lane];
                u64 w00 = bc2(w4.x), w01 = bc2(w4.y), w10 = bc2(w4.z), w11 = bc2(w4.w);
                #pragma unroll
                for (int P = 0; P < NPAIR; ++P) {
                    ulonglong2 hab = *(const ulonglong2*)(abw + P * 64 + 2 * kk);
                    c10[P] = fma2(hab.x, w00, fma2(hab.y, w10, c10[P]));
                    c11[P] = fma2(hab.x, w01, fma2(hab.y, w11, c11[P]));
                }
            }
            #pragma unroll
            for (int P = 0; P < NPAIR; ++P) { c10[P] = relu2(c10[P]); c11[P] = relu2(c11[P]); }
            #pragma unroll
            for (int d = 0; d < 3; ++d) {
                u64 wA = bc2(swc2[lane * 3 + d]);
                u64 wB = bc2(swc2[(lane + 32) * 3 + d]);
                #pragma unroll
                for (int P = 0; P < NPAIR; ++P) {
                    u64 s = allsum2(fma2(c10[P], wA, mul2(c11[P], wB)));
                    float r0, r1; upk(s, r0, r1);
                    if (lane == d) {
                        out[(size_t)NPTS * 22 + (size_t)(pbase + P * 2 + 0) * 3 + d] = sigm(r0);
                        out[(size_t)NPTS * 22 + (size_t)(pbase + P * 2 + 1) * 3 + d] = sigm(r1);
                    }
                }
            }
        }
        __syncwarp();
    }
}

extern "C" void kernel_launch(void* const* d_in, const int* in_sizes, int n_in,
                              void* d_out, int out_size) {
    (void)in_sizes; (void)n_in; (void)out_size;
    HGParams prm;
    double pls = exp2(log2(2048.0 * 1.0 / 16.0) / 15.0);
    for (int l = 0; l < 16; ++l) {
        int r = (int)floor(16.0 * pow(pls, (double)l));
        prm.res[l] = r;
        long long r3 = (long long)r * r * r;
        prm.dense[l] = (r3 <= (long long)TSZ) ? 1 : 0;
    }
    size_t smemBytes = (size_t)SMEM_FLOATS * sizeof(float);
    cudaFuncSetAttribute(nerf_kernel, cudaFuncAttributeMaxDynamicSharedMemorySize, (int)smemBytes);
    nerf_kernel<<<NBLOCKS, NTHREADS, smemBytes>>>(
        (const float*)d_in[0], (const float*)d_in[1],
        (const float*)d_in[2], (const float*)d_in[3],
        (const float*)d_in[4], (const float*)d_in[5], (const float*)d_in[6],
        (const float*)d_in[7], (const float*)d_in[8],
        (const float*)d_in[9], (const float*)d_in[10],
        (const float*)d_in[11], (const float*)d_in[12],
        (float*)d_out, prm);
}